// round 1
// baseline (speedup 1.0000x reference)
#include <cuda_runtime.h>
#include <math.h>

// ---------------------------------------------------------------------------
// Problem constants
// ---------------------------------------------------------------------------
namespace {
constexpr int NTOK   = 196;
constexpr int NBATCH = 8;
constexpr int NN     = NTOK * NTOK;        // 38416
constexpr int MTOT   = NBATCH * NN;        // 307328  (== 2401 * 128, == 38416 * 8)
constexpr int INDIM  = 2048;
constexpr int C0     = 256;
constexpr int C1     = 128;
constexpr int C2     = 64;
}

// ---------------------------------------------------------------------------
// Scratch (static device globals; no runtime allocation)
// ---------------------------------------------------------------------------
__device__ float g_sub [NBATCH * NTOK * C0];          // 1.6 MB  [1568,256]
__device__ float g_pair[(long long)MTOT * C0];        // 315 MB  [M,256]
__device__ float g_s1  [(long long)MTOT * C1];        // 157 MB  [M,128] (branch0 X0a, then conv1 out)
__device__ float g_s2  [(long long)MTOT * C2];        //  79 MB  [M,64]  (branch0 X0b, then conv2 out)
__device__ float g_L0  [MTOT];                        // branch0 logits
__device__ float g_L1  [MTOT];                        // branch1 logits
__device__ float g_Mc  [MTOT];                        // combined softmax map
__device__ float g_stats[32];                         // [2 arrays][8 batches][max,sum]

// ---------------------------------------------------------------------------
// Generic guarded SGEMM: C[M,N] = op(A[M,K] @ B[K,N] + bias), optional batch z
// BM=128, BK=8, TM=8; BN/TN template (128/8 or 64/4) -> 256 threads either way
// ---------------------------------------------------------------------------
template<int BN, int TN, bool RELU, bool HASBIAS>
__global__ void __launch_bounds__(256)
sgemm_k(const float* __restrict__ A, const float* __restrict__ B,
        const float* __restrict__ bias, float* __restrict__ C,
        int M, int K, int N, long long sA, long long sB, long long sC)
{
    constexpr int BM = 128, BK = 8, TM = 8;
    constexpr int TX  = BN / TN;             // 16
    constexpr int BLF = (BK * BN) / 256;     // 4 (BN=128) or 2 (BN=64)

    A += (long long)blockIdx.z * sA;
    B += (long long)blockIdx.z * sB;
    C += (long long)blockIdx.z * sC;

    const int tid = threadIdx.x;
    const int tx  = tid % TX;
    const int ty  = tid / TX;
    const int m0  = blockIdx.x * BM;
    const int n0  = blockIdx.y * BN;

    __shared__ float As[2][BK][BM + 4];
    __shared__ float Bs[2][BK][BN];

    const int ar = tid >> 1;                 // A row within tile (0..127)
    const int ak = (tid & 1) * 4;            // A k offset (0 or 4)
    const int bk = tid >> 5;                 // B k row (0..7)
    const int bc = (tid & 31) * BLF;         // B col offset

    float aReg[4];
    float bReg[BLF];
    float acc[TM][TN];
    #pragma unroll
    for (int i = 0; i < TM; i++)
        #pragma unroll
        for (int j = 0; j < TN; j++) acc[i][j] = 0.f;

    const int nk = (K + BK - 1) / BK;

    auto loadA = [&](int kt) {
        const int m = m0 + ar;
        const int k = kt * BK + ak;
        if (m < M && (k + 3) < K) {
            const float4 v = *reinterpret_cast<const float4*>(A + (long long)m * K + k);
            aReg[0] = v.x; aReg[1] = v.y; aReg[2] = v.z; aReg[3] = v.w;
        } else {
            #pragma unroll
            for (int c = 0; c < 4; c++)
                aReg[c] = (m < M && (k + c) < K) ? A[(long long)m * K + k + c] : 0.f;
        }
    };
    auto loadB = [&](int kt) {
        const int k = kt * BK + bk;
        if (k < K) {
            if constexpr (BLF == 4) {
                const float4 v = *reinterpret_cast<const float4*>(B + (long long)k * N + n0 + bc);
                bReg[0] = v.x; bReg[1] = v.y; bReg[2] = v.z; bReg[3] = v.w;
            } else {
                const float2 v = *reinterpret_cast<const float2*>(B + (long long)k * N + n0 + bc);
                bReg[0] = v.x; bReg[1] = v.y;
            }
        } else {
            #pragma unroll
            for (int c = 0; c < BLF; c++) bReg[c] = 0.f;
        }
    };
    auto stS = [&](int buf) {
        #pragma unroll
        for (int c = 0; c < 4; c++) As[buf][ak + c][ar] = aReg[c];
        #pragma unroll
        for (int c = 0; c < BLF; c++) Bs[buf][bk][bc + c] = bReg[c];
    };

    loadA(0); loadB(0); stS(0);
    __syncthreads();

    for (int kt = 0; kt < nk; ++kt) {
        const int cur = kt & 1;
        if (kt + 1 < nk) { loadA(kt + 1); loadB(kt + 1); }
        #pragma unroll
        for (int kk = 0; kk < BK; ++kk) {
            float a[TM], b[TN];
            #pragma unroll
            for (int c = 0; c < 4; c++) {
                a[c]     = As[cur][kk][ty * 4 + c];
                a[4 + c] = As[cur][kk][ty * 4 + 64 + c];
            }
            if constexpr (TN == 8) {
                #pragma unroll
                for (int c = 0; c < 4; c++) {
                    b[c]     = Bs[cur][kk][tx * 4 + c];
                    b[4 + c] = Bs[cur][kk][tx * 4 + 64 + c];
                }
            } else {
                #pragma unroll
                for (int c = 0; c < TN; c++) b[c] = Bs[cur][kk][tx * 4 + c];
            }
            #pragma unroll
            for (int i = 0; i < TM; i++)
                #pragma unroll
                for (int j = 0; j < TN; j++)
                    acc[i][j] = fmaf(a[i], b[j], acc[i][j]);
        }
        if (kt + 1 < nk) stS(cur ^ 1);
        __syncthreads();
    }

    #pragma unroll
    for (int i = 0; i < TM; i++) {
        const int r = ty * 4 + (i & 3) + ((i >= 4) ? 64 : 0);
        const int m = m0 + r;
        if (m >= M) continue;
        #pragma unroll
        for (int j = 0; j < TN; j++) {
            const int col = tx * 4 + (j & 3) + ((j >= 4 && TN == 8) ? 64 : 0);
            const int n = n0 + col;
            float v = acc[i][j];
            if constexpr (HASBIAS) v += bias[n];
            if constexpr (RELU)    v = fmaxf(v, 0.f);
            C[(long long)m * N + n] = v;
        }
    }
}

// ---------------------------------------------------------------------------
// Implicit-GEMM dilated 3x3 conv (SAME pad, H-dil=1, W-dil=DILW), relu output.
// Input [B,196,196,CIN], weight [3,3,CIN,COUT] (== [9*CIN, COUT] row-major).
// M = MTOT (divisible by 128, no guards). One block = 128 pixels x COUT chans.
// ---------------------------------------------------------------------------
template<int CIN, int COUT, int DILW>
__global__ void __launch_bounds__(256)
conv_k(const float* __restrict__ In, const float* __restrict__ W,
       const float* __restrict__ bias, float* __restrict__ Out)
{
    constexpr int BM = 128, BK = 8, TM = 8;
    constexpr int BN = COUT;
    constexpr int TN = (COUT == 128) ? 8 : 4;
    constexpr int TX = BN / TN;              // 16
    constexpr int BLF = (BK * BN) / 256;     // 4 or 2
    constexpr int KT = CIN / BK;             // 32 or 16

    const int tid = threadIdx.x;
    const int tx  = tid % TX;
    const int ty  = tid / TX;
    const int m0  = blockIdx.x * BM;

    __shared__ float As[2][BK][BM + 4];
    __shared__ float Bs[2][BK][BN];
    __shared__ int   rowbase[BM];

    const int ar = tid >> 1;
    const int ak = (tid & 1) * 4;
    const int bk = tid >> 5;
    const int bc = (tid & 31) * BLF;

    int pb = 0, pi = 0, pj = 0;
    if (tid < BM) {
        const int m = m0 + tid;
        pb = m / NN;
        const int r = m - pb * NN;
        pi = r / NTOK;
        pj = r - pi * NTOK;
    }

    float acc[TM][TN];
    #pragma unroll
    for (int i = 0; i < TM; i++)
        #pragma unroll
        for (int j = 0; j < TN; j++) acc[i][j] = 0.f;

    float aReg[4], bReg[BLF];

    auto loadA = [&](int kt) {
        const int base = rowbase[ar];
        const int k = kt * BK + ak;
        if (base >= 0) {
            const float4 v = *reinterpret_cast<const float4*>(In + base + k);
            aReg[0] = v.x; aReg[1] = v.y; aReg[2] = v.z; aReg[3] = v.w;
        } else {
            aReg[0] = aReg[1] = aReg[2] = aReg[3] = 0.f;
        }
    };

    for (int tap = 0; tap < 9; ++tap) {
        const int p = tap / 3 - 1;
        const int q = tap % 3 - 1;
        if (tid < BM) {
            const int ii = pi + p;
            const int jj = pj + q * DILW;
            rowbase[tid] = (ii >= 0 && ii < NTOK && jj >= 0 && jj < NTOK)
                         ? ((pb * NTOK + ii) * NTOK + jj) * CIN : -1;
        }
        __syncthreads();
        const float* Wt = W + tap * CIN * COUT;

        auto loadB = [&](int kt) {
            const int k = kt * BK + bk;
            if constexpr (BLF == 4) {
                const float4 v = *reinterpret_cast<const float4*>(Wt + k * COUT + bc);
                bReg[0] = v.x; bReg[1] = v.y; bReg[2] = v.z; bReg[3] = v.w;
            } else {
                const float2 v = *reinterpret_cast<const float2*>(Wt + k * COUT + bc);
                bReg[0] = v.x; bReg[1] = v.y;
            }
        };
        auto stS = [&](int buf) {
            #pragma unroll
            for (int c = 0; c < 4; c++) As[buf][ak + c][ar] = aReg[c];
            #pragma unroll
            for (int c = 0; c < BLF; c++) Bs[buf][bk][bc + c] = bReg[c];
        };

        loadA(0); loadB(0); stS(0);
        __syncthreads();

        for (int kt = 0; kt < KT; ++kt) {
            const int cur = kt & 1;
            if (kt + 1 < KT) { loadA(kt + 1); loadB(kt + 1); }
            #pragma unroll
            for (int kk = 0; kk < BK; ++kk) {
                float a[TM], b[TN];
                #pragma unroll
                for (int c = 0; c < 4; c++) {
                    a[c]     = As[cur][kk][ty * 4 + c];
                    a[4 + c] = As[cur][kk][ty * 4 + 64 + c];
                }
                if constexpr (TN == 8) {
                    #pragma unroll
                    for (int c = 0; c < 4; c++) {
                        b[c]     = Bs[cur][kk][tx * 4 + c];
                        b[4 + c] = Bs[cur][kk][tx * 4 + 64 + c];
                    }
                } else {
                    #pragma unroll
                    for (int c = 0; c < TN; c++) b[c] = Bs[cur][kk][tx * 4 + c];
                }
                #pragma unroll
                for (int i = 0; i < TM; i++)
                    #pragma unroll
                    for (int j = 0; j < TN; j++)
                        acc[i][j] = fmaf(a[i], b[j], acc[i][j]);
            }
            if (kt + 1 < KT) stS(cur ^ 1);
            __syncthreads();
        }
    }

    #pragma unroll
    for (int i = 0; i < TM; i++) {
        const int r = ty * 4 + (i & 3) + ((i >= 4) ? 64 : 0);
        const long long m = m0 + r;
        #pragma unroll
        for (int j = 0; j < TN; j++) {
            const int col = tx * 4 + (j & 3) + ((j >= 4 && TN == 8) ? 64 : 0);
            Out[m * COUT + col] = fmaxf(acc[i][j] + bias[col], 0.f);
        }
    }
}

// ---------------------------------------------------------------------------
// Last conv (CIN=64 -> 1 channel, dil DILW): one warp per output pixel.
// ---------------------------------------------------------------------------
template<int CIN, int DILW>
__global__ void convlast_k(const float* __restrict__ In, const float* __restrict__ W,
                           const float* __restrict__ bias, float* __restrict__ Out)
{
    const int lane = threadIdx.x & 31;
    const int wp   = threadIdx.x >> 5;
    const int m    = blockIdx.x * 8 + wp;
    const int b = m / NN;
    const int r = m - b * NN;
    const int i = r / NTOK;
    const int j = r - i * NTOK;
    float acc = 0.f;
    #pragma unroll
    for (int tap = 0; tap < 9; ++tap) {
        const int p = tap / 3 - 1, q = tap % 3 - 1;
        const int ii = i + p, jj = j + q * DILW;
        if (ii >= 0 && ii < NTOK && jj >= 0 && jj < NTOK) {
            const float* src = In + (long long)((b * NTOK + ii) * NTOK + jj) * CIN;
            const float* w   = W + tap * CIN;
            acc = fmaf(src[lane],      w[lane],      acc);
            acc = fmaf(src[lane + 32], w[lane + 32], acc);
        }
    }
    #pragma unroll
    for (int off = 16; off; off >>= 1) acc += __shfl_xor_sync(0xffffffffu, acc, off);
    if (lane == 0) Out[m] = fmaxf(acc + bias[0], 0.f);
}

// branch0 third layer: relu(X[m,0:64] . w03 + b03), warp per pixel
__global__ void dot64_k(const float* __restrict__ X, const float* __restrict__ w,
                        const float* __restrict__ b, float* __restrict__ out)
{
    const int lane = threadIdx.x & 31;
    const int wp   = threadIdx.x >> 5;
    const int m    = blockIdx.x * 8 + wp;
    const float* src = X + (long long)m * 64;
    float acc = fmaf(src[lane], w[lane], src[lane + 32] * w[lane + 32]);
    #pragma unroll
    for (int off = 16; off; off >>= 1) acc += __shfl_xor_sync(0xffffffffu, acc, off);
    if (lane == 0) out[m] = fmaxf(acc + b[0], 0.f);
}

// pair[m,c] = sub[b,i,c] * sub[b,j,c]
__global__ void pair_k()
{
    const long long idx = (long long)blockIdx.x * 256 + threadIdx.x;  // MTOT*64 float4s
    const int m  = (int)(idx >> 6);
    const int c4 = (int)(idx & 63);
    const int b = m / NN;
    const int r = m - b * NN;
    const int i = r / NTOK;
    const int j = r - i * NTOK;
    const float4 va = *reinterpret_cast<const float4*>(g_sub + (b * NTOK + i) * C0 + c4 * 4);
    const float4 vb = *reinterpret_cast<const float4*>(g_sub + (b * NTOK + j) * C0 + c4 * 4);
    float4 o;
    o.x = va.x * vb.x; o.y = va.y * vb.y; o.z = va.z * vb.z; o.w = va.w * vb.w;
    *reinterpret_cast<float4*>(g_pair + (long long)m * C0 + c4 * 4) = o;
}

// softmax stats over symmetrized logits S[i,j] = L[i,j] + L[j,i], per batch
__global__ void smax_stats_k()
{
    const int b = blockIdx.x;
    const float* Lb = (blockIdx.y ? g_L1 : g_L0) + b * NN;
    __shared__ float red[256];
    const int tid = threadIdx.x;
    float mx = -1e30f;
    for (int idx = tid; idx < NN; idx += 256) {
        const int i = idx / NTOK, j = idx - (idx / NTOK) * NTOK;
        mx = fmaxf(mx, Lb[idx] + Lb[j * NTOK + i]);
    }
    red[tid] = mx; __syncthreads();
    for (int s = 128; s; s >>= 1) {
        if (tid < s) red[tid] = fmaxf(red[tid], red[tid + s]);
        __syncthreads();
    }
    mx = red[0]; __syncthreads();
    float sum = 0.f;
    for (int idx = tid; idx < NN; idx += 256) {
        const int i = idx / NTOK, j = idx - (idx / NTOK) * NTOK;
        sum += expf(Lb[idx] + Lb[j * NTOK + i] - mx);
    }
    red[tid] = sum; __syncthreads();
    for (int s = 128; s; s >>= 1) {
        if (tid < s) red[tid] += red[tid + s];
        __syncthreads();
    }
    if (tid == 0) {
        g_stats[(blockIdx.y * 8 + b) * 2]     = mx;
        g_stats[(blockIdx.y * 8 + b) * 2 + 1] = red[0];
    }
}

// Mc = 0.5 * (softmax0 + softmax1)
__global__ void combine_k()
{
    const int idx = blockIdx.x * 256 + threadIdx.x;
    if (idx >= MTOT) return;
    const int b = idx / NN;
    const int r = idx - b * NN;
    const int i = r / NTOK;
    const int j = r - i * NTOK;
    const int t = b * NN + j * NTOK + i;
    const float s0 = g_L0[idx] + g_L0[t];
    const float s1 = g_L1[idx] + g_L1[t];
    const float m0 = g_stats[b * 2],      z0 = g_stats[b * 2 + 1];
    const float m1 = g_stats[16 + b * 2], z1 = g_stats[16 + b * 2 + 1];
    g_Mc[idx] = 0.5f * (expf(s0 - m0) / z0 + expf(s1 - m1) / z1);
}

// ---------------------------------------------------------------------------
extern "C" void kernel_launch(void* const* d_in, const int* in_sizes, int n_in,
                              void* d_out, int out_size)
{
    (void)in_sizes; (void)n_in; (void)out_size;
    const float* x     = (const float*)d_in[0];
    const float* w_prj = (const float*)d_in[1];
    const float* b_prj = (const float*)d_in[2];
    const float* w01   = (const float*)d_in[3];
    const float* b01   = (const float*)d_in[4];
    const float* w02   = (const float*)d_in[5];
    const float* b02   = (const float*)d_in[6];
    const float* w03   = (const float*)d_in[7];
    const float* b03   = (const float*)d_in[8];
    const float* w1    = (const float*)d_in[9];
    const float* b1    = (const float*)d_in[10];
    const float* w2    = (const float*)d_in[11];
    const float* b2    = (const float*)d_in[12];
    const float* w3    = (const float*)d_in[13];
    const float* b3    = (const float*)d_in[14];
    float* out = (float*)d_out;

    float *sub, *pair, *s1, *s2, *L0, *L1, *Mc;
    cudaGetSymbolAddress((void**)&sub,  g_sub);
    cudaGetSymbolAddress((void**)&pair, g_pair);
    cudaGetSymbolAddress((void**)&s1,   g_s1);
    cudaGetSymbolAddress((void**)&s2,   g_s2);
    cudaGetSymbolAddress((void**)&L0,   g_L0);
    cudaGetSymbolAddress((void**)&L1,   g_L1);
    cudaGetSymbolAddress((void**)&Mc,   g_Mc);

    // 1. projection: sub = x @ w_prj + b_prj          [1568,2048]x[2048,256]
    sgemm_k<128, 8, false, true><<<dim3(13, 2, 1), 256>>>(
        x, w_prj, b_prj, sub, NBATCH * NTOK, INDIM, C0, 0, 0, 0);

    // 2. pair tensor
    pair_k<<<MTOT * 64 / 256, 256>>>();

    // 3. branch 0: pointwise chain (uses s1/s2 as scratch, before convs)
    sgemm_k<128, 8, true, true><<<dim3(MTOT / 128, 1, 1), 256>>>(
        pair, w01, b01, s1, MTOT, C0, C1, 0, 0, 0);
    sgemm_k<64, 4, true, true><<<dim3(MTOT / 128, 1, 1), 256>>>(
        s1, w02, b02, s2, MTOT, C1, C2, 0, 0, 0);
    dot64_k<<<MTOT / 8, 256>>>(s2, w03, b03, L0);

    // 4. branch 1: dilated convs (overwrite s1/s2)
    conv_k<256, 128, 1><<<MTOT / 128, 256>>>(pair, w1, b1, s1);
    conv_k<128,  64, 2><<<MTOT / 128, 256>>>(s1,   w2, b2, s2);
    convlast_k<64, 4><<<MTOT / 8, 256>>>(s2, w3, b3, L1);

    // 5. softmax (symmetrized) + combine maps
    smax_stats_k<<<dim3(8, 2), 256>>>();
    combine_k<<<(MTOT + 255) / 256, 256>>>();

    // 6. aggregation: out[b] = Mc[b] @ x[b]           [196,196]x[196,2048] x8
    sgemm_k<128, 8, false, false><<<dim3(2, 16, 8), 256>>>(
        Mc, x, nullptr, out, NTOK, NTOK, INDIM,
        (long long)NN, (long long)NTOK * INDIM, (long long)NTOK * INDIM);
}

// round 2
// speedup vs baseline: 1.5268x; 1.5268x over previous
#include <cuda_runtime.h>
#include <math.h>

// ---------------------------------------------------------------------------
// Problem constants
// ---------------------------------------------------------------------------
namespace {
constexpr int NTOK   = 196;
constexpr int NBATCH = 8;
constexpr int NN     = NTOK * NTOK;        // 38416
constexpr int MTOT   = NBATCH * NN;        // 307328  (== 2401 * 128)
constexpr int INDIM  = 2048;
constexpr int C0     = 256;
constexpr int C1     = 128;
constexpr int C2     = 64;
}

// ---------------------------------------------------------------------------
// Scratch (static device globals; no runtime allocation)
// ---------------------------------------------------------------------------
__device__ float g_sub [NBATCH * NTOK * C0];          // 1.6 MB  [1568,256]
__device__ float g_s1  [(long long)MTOT * C1];        // 157 MB  (branch0 X0a, then conv1 out)
__device__ float g_s2  [(long long)MTOT * C2];        //  79 MB  (branch0 X0b, then conv2 out)
__device__ float g_L0  [MTOT];                        // branch0 logits
__device__ float g_L1  [MTOT];                        // branch1 logits
__device__ float g_Mc  [MTOT];                        // combined softmax map
__device__ float g_stats[32];                         // [2 arrays][8 batches][max,sum]

// ---------------------------------------------------------------------------
// Generic guarded SGEMM: C[M,N] = op(A[M,K] @ B[K,N] + bias), optional batch z
// ---------------------------------------------------------------------------
template<int BN, int TN, bool RELU, bool HASBIAS>
__global__ void __launch_bounds__(256)
sgemm_k(const float* __restrict__ A, const float* __restrict__ B,
        const float* __restrict__ bias, float* __restrict__ C,
        int M, int K, int N, long long sA, long long sB, long long sC)
{
    constexpr int BM = 128, BK = 8, TM = 8;
    constexpr int TX  = BN / TN;             // 16
    constexpr int BLF = (BK * BN) / 256;     // 4 (BN=128) or 2 (BN=64)

    A += (long long)blockIdx.z * sA;
    B += (long long)blockIdx.z * sB;
    C += (long long)blockIdx.z * sC;

    const int tid = threadIdx.x;
    const int tx  = tid % TX;
    const int ty  = tid / TX;
    const int m0  = blockIdx.x * BM;
    const int n0  = blockIdx.y * BN;

    __shared__ float As[2][BK][BM + 4];
    __shared__ float Bs[2][BK][BN];

    const int ar = tid >> 1;
    const int ak = (tid & 1) * 4;
    const int bk = tid >> 5;
    const int bc = (tid & 31) * BLF;

    float aReg[4];
    float bReg[BLF];
    float acc[TM][TN];
    #pragma unroll
    for (int i = 0; i < TM; i++)
        #pragma unroll
        for (int j = 0; j < TN; j++) acc[i][j] = 0.f;

    const int nk = (K + BK - 1) / BK;

    auto loadA = [&](int kt) {
        const int m = m0 + ar;
        const int k = kt * BK + ak;
        if (m < M && (k + 3) < K) {
            const float4 v = *reinterpret_cast<const float4*>(A + (long long)m * K + k);
            aReg[0] = v.x; aReg[1] = v.y; aReg[2] = v.z; aReg[3] = v.w;
        } else {
            #pragma unroll
            for (int c = 0; c < 4; c++)
                aReg[c] = (m < M && (k + c) < K) ? A[(long long)m * K + k + c] : 0.f;
        }
    };
    auto loadB = [&](int kt) {
        const int k = kt * BK + bk;
        if (k < K) {
            if constexpr (BLF == 4) {
                const float4 v = *reinterpret_cast<const float4*>(B + (long long)k * N + n0 + bc);
                bReg[0] = v.x; bReg[1] = v.y; bReg[2] = v.z; bReg[3] = v.w;
            } else {
                const float2 v = *reinterpret_cast<const float2*>(B + (long long)k * N + n0 + bc);
                bReg[0] = v.x; bReg[1] = v.y;
            }
        } else {
            #pragma unroll
            for (int c = 0; c < BLF; c++) bReg[c] = 0.f;
        }
    };
    auto stS = [&](int buf) {
        #pragma unroll
        for (int c = 0; c < 4; c++) As[buf][ak + c][ar] = aReg[c];
        #pragma unroll
        for (int c = 0; c < BLF; c++) Bs[buf][bk][bc + c] = bReg[c];
    };

    loadA(0); loadB(0); stS(0);
    __syncthreads();

    for (int kt = 0; kt < nk; ++kt) {
        const int cur = kt & 1;
        if (kt + 1 < nk) { loadA(kt + 1); loadB(kt + 1); }
        #pragma unroll
        for (int kk = 0; kk < BK; ++kk) {
            float a[TM], b[TN];
            #pragma unroll
            for (int c = 0; c < 4; c++) {
                a[c]     = As[cur][kk][ty * 4 + c];
                a[4 + c] = As[cur][kk][ty * 4 + 64 + c];
            }
            if constexpr (TN == 8) {
                #pragma unroll
                for (int c = 0; c < 4; c++) {
                    b[c]     = Bs[cur][kk][tx * 4 + c];
                    b[4 + c] = Bs[cur][kk][tx * 4 + 64 + c];
                }
            } else {
                #pragma unroll
                for (int c = 0; c < TN; c++) b[c] = Bs[cur][kk][tx * 4 + c];
            }
            #pragma unroll
            for (int i = 0; i < TM; i++)
                #pragma unroll
                for (int j = 0; j < TN; j++)
                    acc[i][j] = fmaf(a[i], b[j], acc[i][j]);
        }
        if (kt + 1 < nk) stS(cur ^ 1);
        __syncthreads();
    }

    #pragma unroll
    for (int i = 0; i < TM; i++) {
        const int r = ty * 4 + (i & 3) + ((i >= 4) ? 64 : 0);
        const int m = m0 + r;
        if (m >= M) continue;
        #pragma unroll
        for (int j = 0; j < TN; j++) {
            const int col = tx * 4 + (j & 3) + ((j >= 4 && TN == 8) ? 64 : 0);
            const int n = n0 + col;
            float v = acc[i][j];
            if constexpr (HASBIAS) v += bias[n];
            if constexpr (RELU)    v = fmaxf(v, 0.f);
            C[(long long)m * N + n] = v;
        }
    }
}

// ---------------------------------------------------------------------------
// Branch0 first GEMM with on-the-fly pair A-tile:
// A[m,c] = sub[b,i,c]*sub[b,j,c], m=(b,i,j). M=MTOT (no guards), K=256, N=128.
// C = relu(A @ w01 + b01)
// ---------------------------------------------------------------------------
__global__ void __launch_bounds__(256)
sgemm_pair_k(const float* __restrict__ sub, const float* __restrict__ B,
             const float* __restrict__ bias, float* __restrict__ C)
{
    constexpr int BM = 128, BN = 128, BK = 8, TM = 8, TN = 8, TX = 16;
    constexpr int K = C0, N = C1;

    const int tid = threadIdx.x;
    const int tx  = tid % TX;
    const int ty  = tid / TX;
    const int m0  = blockIdx.x * BM;

    __shared__ float As[2][BK][BM + 4];
    __shared__ float Bs[2][BK][BN];

    const int ar = tid >> 1;
    const int ak = (tid & 1) * 4;
    const int bk = tid >> 5;
    const int bc = (tid & 31) * 4;

    // fixed row -> (b,i,j) pointers
    const int m = m0 + ar;
    const int pb = m / NN;
    const int pr = m - pb * NN;
    const int pi = pr / NTOK;
    const int pj = pr - pi * NTOK;
    const float* rowI = sub + (long long)(pb * NTOK + pi) * C0;
    const float* rowJ = sub + (long long)(pb * NTOK + pj) * C0;

    float aReg[4], bReg[4];
    float acc[TM][TN];
    #pragma unroll
    for (int i = 0; i < TM; i++)
        #pragma unroll
        for (int j = 0; j < TN; j++) acc[i][j] = 0.f;

    constexpr int nk = K / BK;  // 32

    auto loadA = [&](int kt) {
        const int k = kt * BK + ak;
        const float4 va = *reinterpret_cast<const float4*>(rowI + k);
        const float4 vb = *reinterpret_cast<const float4*>(rowJ + k);
        aReg[0] = va.x * vb.x; aReg[1] = va.y * vb.y;
        aReg[2] = va.z * vb.z; aReg[3] = va.w * vb.w;
    };
    auto loadB = [&](int kt) {
        const int k = kt * BK + bk;
        const float4 v = *reinterpret_cast<const float4*>(B + (long long)k * N + bc);
        bReg[0] = v.x; bReg[1] = v.y; bReg[2] = v.z; bReg[3] = v.w;
    };
    auto stS = [&](int buf) {
        #pragma unroll
        for (int c = 0; c < 4; c++) As[buf][ak + c][ar] = aReg[c];
        #pragma unroll
        for (int c = 0; c < 4; c++) Bs[buf][bk][bc + c] = bReg[c];
    };

    loadA(0); loadB(0); stS(0);
    __syncthreads();

    for (int kt = 0; kt < nk; ++kt) {
        const int cur = kt & 1;
        if (kt + 1 < nk) { loadA(kt + 1); loadB(kt + 1); }
        #pragma unroll
        for (int kk = 0; kk < BK; ++kk) {
            float a[TM], b[TN];
            #pragma unroll
            for (int c = 0; c < 4; c++) {
                a[c]     = As[cur][kk][ty * 4 + c];
                a[4 + c] = As[cur][kk][ty * 4 + 64 + c];
                b[c]     = Bs[cur][kk][tx * 4 + c];
                b[4 + c] = Bs[cur][kk][tx * 4 + 64 + c];
            }
            #pragma unroll
            for (int i = 0; i < TM; i++)
                #pragma unroll
                for (int j = 0; j < TN; j++)
                    acc[i][j] = fmaf(a[i], b[j], acc[i][j]);
        }
        if (kt + 1 < nk) stS(cur ^ 1);
        __syncthreads();
    }

    #pragma unroll
    for (int i = 0; i < TM; i++) {
        const int r = ty * 4 + (i & 3) + ((i >= 4) ? 64 : 0);
        const long long mm = m0 + r;
        #pragma unroll
        for (int j = 0; j < TN; j++) {
            const int col = tx * 4 + (j & 3) + ((j >= 4) ? 64 : 0);
            C[mm * N + col] = fmaxf(acc[i][j] + bias[col], 0.f);
        }
    }
}

// ---------------------------------------------------------------------------
// Factorized conv1 (3x3, dil 1, 256->128, relu):
//   out[b,i,j,d] = relu(b1[d] + sum_{q,c} Sq[j,(q,c)] * H_i[(q,c),d])
//   Sq[j,(q,c)]  = sub[b,j+q-1,c]            (0 out of bounds)
//   H_i[(q,c),d] = sum_p sub[b,i+p-1,c] * w1[p,q,c,d]   (computed in B loader)
// One block: (b,i) = blockIdx.z, j-tile = blockIdx.x (128 rows; 196 total).
// K = 3*256 = 768. FLOPs: 60 GF vs 181 GF direct.
// ---------------------------------------------------------------------------
__global__ void __launch_bounds__(256)
conv1f_k(const float* __restrict__ sub, const float* __restrict__ W,
         const float* __restrict__ bias, float* __restrict__ Out)
{
    constexpr int BM = 128, BN = 128, BK = 8, TM = 8, TN = 8, TX = 16;
    constexpr int K = 3 * C0;   // 768
    constexpr int nk = K / BK;  // 96

    const int tid = threadIdx.x;
    const int tx  = tid % TX;
    const int ty  = tid / TX;
    const int z   = blockIdx.z;           // b*196 + i
    const int b   = z / NTOK;
    const int i   = z - b * NTOK;
    const int m0  = blockIdx.x * BM;      // j tile base

    const float* subB = sub + (long long)b * NTOK * C0;

    __shared__ float As[2][BK][BM + 4];
    __shared__ float Bs[2][BK][BN];

    const int ar = tid >> 1;
    const int ak = (tid & 1) * 4;
    const int bk = tid >> 5;
    const int bc = (tid & 31) * 4;

    // valid p taps for this i (uniform across block)
    const bool pv0 = (i - 1 >= 0);
    const bool pv2 = (i + 1 < NTOK);
    const float* srow0 = subB + (i - 1) * C0;
    const float* srow1 = subB + i * C0;
    const float* srow2 = subB + (i + 1) * C0;

    float aReg[4], bReg[4];
    float acc[TM][TN];
    #pragma unroll
    for (int ii = 0; ii < TM; ii++)
        #pragma unroll
        for (int jj = 0; jj < TN; jj++) acc[ii][jj] = 0.f;

    auto loadA = [&](int kt) {
        const int j = m0 + ar;
        const int k = kt * BK + ak;
        const int q = k >> 8;
        const int c = k & 255;
        const int jj = j + q - 1;
        if (j < NTOK && jj >= 0 && jj < NTOK) {
            const float4 v = *reinterpret_cast<const float4*>(subB + jj * C0 + c);
            aReg[0] = v.x; aReg[1] = v.y; aReg[2] = v.z; aReg[3] = v.w;
        } else {
            aReg[0] = aReg[1] = aReg[2] = aReg[3] = 0.f;
        }
    };
    auto loadB = [&](int kt) {
        const int k = kt * BK + bk;
        const int q = k >> 8;
        const int c = k & 255;
        float4 r = make_float4(0.f, 0.f, 0.f, 0.f);
        // p = 1 (always valid)
        {
            const float s = srow1[c];
            const float4 w = *reinterpret_cast<const float4*>(W + ((size_t)(3 + q) * C0 + c) * C1 + bc);
            r.x = fmaf(s, w.x, r.x); r.y = fmaf(s, w.y, r.y);
            r.z = fmaf(s, w.z, r.z); r.w = fmaf(s, w.w, r.w);
        }
        if (pv0) {
            const float s = srow0[c];
            const float4 w = *reinterpret_cast<const float4*>(W + ((size_t)q * C0 + c) * C1 + bc);
            r.x = fmaf(s, w.x, r.x); r.y = fmaf(s, w.y, r.y);
            r.z = fmaf(s, w.z, r.z); r.w = fmaf(s, w.w, r.w);
        }
        if (pv2) {
            const float s = srow2[c];
            const float4 w = *reinterpret_cast<const float4*>(W + ((size_t)(6 + q) * C0 + c) * C1 + bc);
            r.x = fmaf(s, w.x, r.x); r.y = fmaf(s, w.y, r.y);
            r.z = fmaf(s, w.z, r.z); r.w = fmaf(s, w.w, r.w);
        }
        bReg[0] = r.x; bReg[1] = r.y; bReg[2] = r.z; bReg[3] = r.w;
    };
    auto stS = [&](int buf) {
        #pragma unroll
        for (int c = 0; c < 4; c++) As[buf][ak + c][ar] = aReg[c];
        #pragma unroll
        for (int c = 0; c < 4; c++) Bs[buf][bk][bc + c] = bReg[c];
    };

    loadA(0); loadB(0); stS(0);
    __syncthreads();

    for (int kt = 0; kt < nk; ++kt) {
        const int cur = kt & 1;
        if (kt + 1 < nk) { loadA(kt + 1); loadB(kt + 1); }
        #pragma unroll
        for (int kk = 0; kk < BK; ++kk) {
            float a[TM], bv[TN];
            #pragma unroll
            for (int c = 0; c < 4; c++) {
                a[c]      = As[cur][kk][ty * 4 + c];
                a[4 + c]  = As[cur][kk][ty * 4 + 64 + c];
                bv[c]     = Bs[cur][kk][tx * 4 + c];
                bv[4 + c] = Bs[cur][kk][tx * 4 + 64 + c];
            }
            #pragma unroll
            for (int ii = 0; ii < TM; ii++)
                #pragma unroll
                for (int jj = 0; jj < TN; jj++)
                    acc[ii][jj] = fmaf(a[ii], bv[jj], acc[ii][jj]);
        }
        if (kt + 1 < nk) stS(cur ^ 1);
        __syncthreads();
    }

    #pragma unroll
    for (int ii = 0; ii < TM; ii++) {
        const int r = ty * 4 + (ii & 3) + ((ii >= 4) ? 64 : 0);
        const int j = m0 + r;
        if (j >= NTOK) continue;
        const long long mm = (long long)b * NN + (long long)i * NTOK + j;
        #pragma unroll
        for (int jj = 0; jj < TN; jj++) {
            const int col = tx * 4 + (jj & 3) + ((jj >= 4) ? 64 : 0);
            Out[mm * C1 + col] = fmaxf(acc[ii][jj] + bias[col], 0.f);
        }
    }
}

// ---------------------------------------------------------------------------
// Implicit-GEMM dilated 3x3 conv (for conv2: 128->64, W-dil=2), relu output.
// ---------------------------------------------------------------------------
template<int CIN, int COUT, int DILW>
__global__ void __launch_bounds__(256)
conv_k(const float* __restrict__ In, const float* __restrict__ W,
       const float* __restrict__ bias, float* __restrict__ Out)
{
    constexpr int BM = 128, BK = 8, TM = 8;
    constexpr int BN = COUT;
    constexpr int TN = (COUT == 128) ? 8 : 4;
    constexpr int TX = BN / TN;
    constexpr int BLF = (BK * BN) / 256;
    constexpr int KT = CIN / BK;

    const int tid = threadIdx.x;
    const int tx  = tid % TX;
    const int ty  = tid / TX;
    const int m0  = blockIdx.x * BM;

    __shared__ float As[2][BK][BM + 4];
    __shared__ float Bs[2][BK][BN];
    __shared__ int   rowbase[BM];

    const int ar = tid >> 1;
    const int ak = (tid & 1) * 4;
    const int bk = tid >> 5;
    const int bc = (tid & 31) * BLF;

    int pb = 0, pi = 0, pj = 0;
    if (tid < BM) {
        const int m = m0 + tid;
        pb = m / NN;
        const int r = m - pb * NN;
        pi = r / NTOK;
        pj = r - pi * NTOK;
    }

    float acc[TM][TN];
    #pragma unroll
    for (int i = 0; i < TM; i++)
        #pragma unroll
        for (int j = 0; j < TN; j++) acc[i][j] = 0.f;

    float aReg[4], bReg[BLF];

    auto loadA = [&](int kt) {
        const int base = rowbase[ar];
        const int k = kt * BK + ak;
        if (base >= 0) {
            const float4 v = *reinterpret_cast<const float4*>(In + base + k);
            aReg[0] = v.x; aReg[1] = v.y; aReg[2] = v.z; aReg[3] = v.w;
        } else {
            aReg[0] = aReg[1] = aReg[2] = aReg[3] = 0.f;
        }
    };

    for (int tap = 0; tap < 9; ++tap) {
        const int p = tap / 3 - 1;
        const int q = tap % 3 - 1;
        if (tid < BM) {
            const int ii = pi + p;
            const int jj = pj + q * DILW;
            rowbase[tid] = (ii >= 0 && ii < NTOK && jj >= 0 && jj < NTOK)
                         ? ((pb * NTOK + ii) * NTOK + jj) * CIN : -1;
        }
        __syncthreads();
        const float* Wt = W + tap * CIN * COUT;

        auto loadB = [&](int kt) {
            const int k = kt * BK + bk;
            if constexpr (BLF == 4) {
                const float4 v = *reinterpret_cast<const float4*>(Wt + k * COUT + bc);
                bReg[0] = v.x; bReg[1] = v.y; bReg[2] = v.z; bReg[3] = v.w;
            } else {
                const float2 v = *reinterpret_cast<const float2*>(Wt + k * COUT + bc);
                bReg[0] = v.x; bReg[1] = v.y;
            }
        };
        auto stS = [&](int buf) {
            #pragma unroll
            for (int c = 0; c < 4; c++) As[buf][ak + c][ar] = aReg[c];
            #pragma unroll
            for (int c = 0; c < BLF; c++) Bs[buf][bk][bc + c] = bReg[c];
        };

        loadA(0); loadB(0); stS(0);
        __syncthreads();

        for (int kt = 0; kt < KT; ++kt) {
            const int cur = kt & 1;
            if (kt + 1 < KT) { loadA(kt + 1); loadB(kt + 1); }
            #pragma unroll
            for (int kk = 0; kk < BK; ++kk) {
                float a[TM], b[TN];
                #pragma unroll
                for (int c = 0; c < 4; c++) {
                    a[c]     = As[cur][kk][ty * 4 + c];
                    a[4 + c] = As[cur][kk][ty * 4 + 64 + c];
                }
                if constexpr (TN == 8) {
                    #pragma unroll
                    for (int c = 0; c < 4; c++) {
                        b[c]     = Bs[cur][kk][tx * 4 + c];
                        b[4 + c] = Bs[cur][kk][tx * 4 + 64 + c];
                    }
                } else {
                    #pragma unroll
                    for (int c = 0; c < TN; c++) b[c] = Bs[cur][kk][tx * 4 + c];
                }
                #pragma unroll
                for (int i = 0; i < TM; i++)
                    #pragma unroll
                    for (int j = 0; j < TN; j++)
                        acc[i][j] = fmaf(a[i], b[j], acc[i][j]);
            }
            if (kt + 1 < KT) stS(cur ^ 1);
            __syncthreads();
        }
    }

    #pragma unroll
    for (int i = 0; i < TM; i++) {
        const int r = ty * 4 + (i & 3) + ((i >= 4) ? 64 : 0);
        const long long m = m0 + r;
        #pragma unroll
        for (int j = 0; j < TN; j++) {
            const int col = tx * 4 + (j & 3) + ((j >= 4 && TN == 8) ? 64 : 0);
            Out[m * COUT + col] = fmaxf(acc[i][j] + bias[col], 0.f);
        }
    }
}

// ---------------------------------------------------------------------------
// Last conv (CIN=64 -> 1 channel, dil DILW): one warp per output pixel.
// ---------------------------------------------------------------------------
template<int CIN, int DILW>
__global__ void convlast_k(const float* __restrict__ In, const float* __restrict__ W,
                           const float* __restrict__ bias, float* __restrict__ Out)
{
    const int lane = threadIdx.x & 31;
    const int wp   = threadIdx.x >> 5;
    const int m    = blockIdx.x * 8 + wp;
    const int b = m / NN;
    const int r = m - b * NN;
    const int i = r / NTOK;
    const int j = r - i * NTOK;
    float acc = 0.f;
    #pragma unroll
    for (int tap = 0; tap < 9; ++tap) {
        const int p = tap / 3 - 1, q = tap % 3 - 1;
        const int ii = i + p, jj = j + q * DILW;
        if (ii >= 0 && ii < NTOK && jj >= 0 && jj < NTOK) {
            const float* src = In + (long long)((b * NTOK + ii) * NTOK + jj) * CIN;
            const float* w   = W + tap * CIN;
            acc = fmaf(src[lane],      w[lane],      acc);
            acc = fmaf(src[lane + 32], w[lane + 32], acc);
        }
    }
    #pragma unroll
    for (int off = 16; off; off >>= 1) acc += __shfl_xor_sync(0xffffffffu, acc, off);
    if (lane == 0) Out[m] = fmaxf(acc + bias[0], 0.f);
}

// branch0 third layer: relu(X[m,0:64] . w03 + b03), warp per pixel
__global__ void dot64_k(const float* __restrict__ X, const float* __restrict__ w,
                        const float* __restrict__ b, float* __restrict__ out)
{
    const int lane = threadIdx.x & 31;
    const int wp   = threadIdx.x >> 5;
    const int m    = blockIdx.x * 8 + wp;
    const float* src = X + (long long)m * 64;
    float acc = fmaf(src[lane], w[lane], src[lane + 32] * w[lane + 32]);
    #pragma unroll
    for (int off = 16; off; off >>= 1) acc += __shfl_xor_sync(0xffffffffu, acc, off);
    if (lane == 0) out[m] = fmaxf(acc + b[0], 0.f);
}

// softmax stats over symmetrized logits S[i,j] = L[i,j] + L[j,i], per batch
__global__ void smax_stats_k()
{
    const int b = blockIdx.x;
    const float* Lb = (blockIdx.y ? g_L1 : g_L0) + b * NN;
    __shared__ float red[256];
    const int tid = threadIdx.x;
    float mx = -1e30f;
    for (int idx = tid; idx < NN; idx += 256) {
        const int i = idx / NTOK, j = idx - (idx / NTOK) * NTOK;
        mx = fmaxf(mx, Lb[idx] + Lb[j * NTOK + i]);
    }
    red[tid] = mx; __syncthreads();
    for (int s = 128; s; s >>= 1) {
        if (tid < s) red[tid] = fmaxf(red[tid], red[tid + s]);
        __syncthreads();
    }
    mx = red[0]; __syncthreads();
    float sum = 0.f;
    for (int idx = tid; idx < NN; idx += 256) {
        const int i = idx / NTOK, j = idx - (idx / NTOK) * NTOK;
        sum += expf(Lb[idx] + Lb[j * NTOK + i] - mx);
    }
    red[tid] = sum; __syncthreads();
    for (int s = 128; s; s >>= 1) {
        if (tid < s) red[tid] += red[tid + s];
        __syncthreads();
    }
    if (tid == 0) {
        g_stats[(blockIdx.y * 8 + b) * 2]     = mx;
        g_stats[(blockIdx.y * 8 + b) * 2 + 1] = red[0];
    }
}

// Mc = 0.5 * (softmax0 + softmax1)
__global__ void combine_k()
{
    const int idx = blockIdx.x * 256 + threadIdx.x;
    if (idx >= MTOT) return;
    const int b = idx / NN;
    const int r = idx - b * NN;
    const int i = r / NTOK;
    const int j = r - i * NTOK;
    const int t = b * NN + j * NTOK + i;
    const float s0 = g_L0[idx] + g_L0[t];
    const float s1 = g_L1[idx] + g_L1[t];
    const float m0 = g_stats[b * 2],      z0 = g_stats[b * 2 + 1];
    const float m1 = g_stats[16 + b * 2], z1 = g_stats[16 + b * 2 + 1];
    g_Mc[idx] = 0.5f * (expf(s0 - m0) / z0 + expf(s1 - m1) / z1);
}

// ---------------------------------------------------------------------------
extern "C" void kernel_launch(void* const* d_in, const int* in_sizes, int n_in,
                              void* d_out, int out_size)
{
    (void)in_sizes; (void)n_in; (void)out_size;
    const float* x     = (const float*)d_in[0];
    const float* w_prj = (const float*)d_in[1];
    const float* b_prj = (const float*)d_in[2];
    const float* w01   = (const float*)d_in[3];
    const float* b01   = (const float*)d_in[4];
    const float* w02   = (const float*)d_in[5];
    const float* b02   = (const float*)d_in[6];
    const float* w03   = (const float*)d_in[7];
    const float* b03   = (const float*)d_in[8];
    const float* w1    = (const float*)d_in[9];
    const float* b1    = (const float*)d_in[10];
    const float* w2    = (const float*)d_in[11];
    const float* b2    = (const float*)d_in[12];
    const float* w3    = (const float*)d_in[13];
    const float* b3    = (const float*)d_in[14];
    float* out = (float*)d_out;

    float *sub, *s1, *s2, *L0, *L1, *Mc;
    cudaGetSymbolAddress((void**)&sub,  g_sub);
    cudaGetSymbolAddress((void**)&s1,   g_s1);
    cudaGetSymbolAddress((void**)&s2,   g_s2);
    cudaGetSymbolAddress((void**)&L0,   g_L0);
    cudaGetSymbolAddress((void**)&L1,   g_L1);
    cudaGetSymbolAddress((void**)&Mc,   g_Mc);

    // 1. projection: sub = x @ w_prj + b_prj          [1568,2048]x[2048,256]
    sgemm_k<128, 8, false, true><<<dim3(13, 2, 1), 256>>>(
        x, w_prj, b_prj, sub, NBATCH * NTOK, INDIM, C0, 0, 0, 0);

    // 2. branch 0: pointwise chain (pair fused into first GEMM's A loader)
    sgemm_pair_k<<<MTOT / 128, 256>>>(sub, w01, b01, s1);
    sgemm_k<64, 4, true, true><<<dim3(MTOT / 128, 1, 1), 256>>>(
        s1, w02, b02, s2, MTOT, C1, C2, 0, 0, 0);
    dot64_k<<<MTOT / 8, 256>>>(s2, w03, b03, L0);

    // 3. branch 1: factorized conv1, then direct conv2/conv3
    conv1f_k<<<dim3(2, 1, NBATCH * NTOK), 256>>>(sub, w1, b1, s1);
    conv_k<128, 64, 2><<<MTOT / 128, 256>>>(s1, w2, b2, s2);
    convlast_k<64, 4><<<MTOT / 8, 256>>>(s2, w3, b3, L1);

    // 4. softmax (symmetrized) + combine maps
    smax_stats_k<<<dim3(8, 2), 256>>>();
    combine_k<<<(MTOT + 255) / 256, 256>>>();

    // 5. aggregation: out[b] = Mc[b] @ x[b]           [196,196]x[196,2048] x8
    sgemm_k<128, 8, false, false><<<dim3(2, 16, 8), 256>>>(
        Mc, x, nullptr, out, NTOK, NTOK, INDIM,
        (long long)NN, (long long)NTOK * INDIM, (long long)NTOK * INDIM);
}

// round 3
// speedup vs baseline: 1.6945x; 1.1099x over previous
#include <cuda_runtime.h>
#include <math.h>

// ---------------------------------------------------------------------------
// Problem constants
// ---------------------------------------------------------------------------
namespace {
constexpr int NTOK   = 196;
constexpr int NBATCH = 8;
constexpr int NN     = NTOK * NTOK;        // 38416
constexpr int MTOT   = NBATCH * NN;        // 307328  (== 2401 * 128)
constexpr int INDIM  = 2048;
constexpr int C0     = 256;
constexpr int C1     = 128;
constexpr int C2     = 64;
}

// ---------------------------------------------------------------------------
// Packed f32x2 helpers (Blackwell FFMA2)
// ---------------------------------------------------------------------------
__device__ __forceinline__ unsigned long long pk2(float x, float y) {
    unsigned long long r;
    asm("mov.b64 %0, {%1, %2};" : "=l"(r) : "f"(x), "f"(y));
    return r;
}
__device__ __forceinline__ void fma2(unsigned long long& d,
                                     unsigned long long a, unsigned long long b) {
    asm("fma.rn.f32x2 %0, %1, %2, %0;" : "+l"(d) : "l"(a), "l"(b));
}
__device__ __forceinline__ float2 upk2(unsigned long long v) {
    float2 f;
    asm("mov.b64 {%0, %1}, %2;" : "=f"(f.x), "=f"(f.y) : "l"(v));
    return f;
}

// ---------------------------------------------------------------------------
// Scratch (static device globals; no runtime allocation)
// ---------------------------------------------------------------------------
__device__ float g_sub [NBATCH * NTOK * C0];          // 1.6 MB  [1568,256]
__device__ float g_s1  [(long long)MTOT * C1];        // 157 MB
__device__ float g_s2  [(long long)MTOT * C2];        //  79 MB
__device__ float g_L0  [MTOT];
__device__ float g_L1  [MTOT];
__device__ float g_Mc  [MTOT];
__device__ float g_stats[32];

// ---------------------------------------------------------------------------
// Generic guarded SGEMM with f32x2 mainloop.
// Row pairing: pair p covers rows {ty*4+2*(p&1)*1.., see epilogue}.
// ---------------------------------------------------------------------------
template<int BN, int TN, bool RELU, bool HASBIAS>
__global__ void __launch_bounds__(256)
sgemm_k(const float* __restrict__ A, const float* __restrict__ B,
        const float* __restrict__ bias, float* __restrict__ C,
        int M, int K, int N, long long sA, long long sB, long long sC)
{
    constexpr int BM = 128, BK = 8;
    constexpr int TX  = BN / TN;             // 16
    constexpr int BLF = (BK * BN) / 256;     // 4 (BN=128) or 2 (BN=64)

    A += (long long)blockIdx.z * sA;
    B += (long long)blockIdx.z * sB;
    C += (long long)blockIdx.z * sC;

    const int tid = threadIdx.x;
    const int tx  = tid % TX;
    const int ty  = tid / TX;
    const int m0  = blockIdx.x * BM;
    const int n0  = blockIdx.y * BN;

    __shared__ __align__(16) float As[2][BK][BM + 4];
    __shared__ __align__(16) float Bs[2][BK][BN];

    const int ar = tid >> 1;
    const int ak = (tid & 1) * 4;
    const int bk = tid >> 5;
    const int bc = (tid & 31) * BLF;

    float aReg[4];
    float bReg[BLF];
    unsigned long long acc2[4][TN];
    #pragma unroll
    for (int p = 0; p < 4; p++)
        #pragma unroll
        for (int j = 0; j < TN; j++) acc2[p][j] = 0ULL;

    const int nk = (K + BK - 1) / BK;

    auto loadA = [&](int kt) {
        const int m = m0 + ar;
        const int k = kt * BK + ak;
        if (m < M && (k + 3) < K) {
            const float4 v = *reinterpret_cast<const float4*>(A + (long long)m * K + k);
            aReg[0] = v.x; aReg[1] = v.y; aReg[2] = v.z; aReg[3] = v.w;
        } else {
            #pragma unroll
            for (int c = 0; c < 4; c++)
                aReg[c] = (m < M && (k + c) < K) ? A[(long long)m * K + k + c] : 0.f;
        }
    };
    auto loadB = [&](int kt) {
        const int k = kt * BK + bk;
        if (k < K) {
            if constexpr (BLF == 4) {
                const float4 v = *reinterpret_cast<const float4*>(B + (long long)k * N + n0 + bc);
                bReg[0] = v.x; bReg[1] = v.y; bReg[2] = v.z; bReg[3] = v.w;
            } else {
                const float2 v = *reinterpret_cast<const float2*>(B + (long long)k * N + n0 + bc);
                bReg[0] = v.x; bReg[1] = v.y;
            }
        } else {
            #pragma unroll
            for (int c = 0; c < BLF; c++) bReg[c] = 0.f;
        }
    };
    auto stS = [&](int buf) {
        #pragma unroll
        for (int c = 0; c < 4; c++) As[buf][ak + c][ar] = aReg[c];
        #pragma unroll
        for (int c = 0; c < BLF; c++) Bs[buf][bk][bc + c] = bReg[c];
    };

    loadA(0); loadB(0); stS(0);
    __syncthreads();

    for (int kt = 0; kt < nk; ++kt) {
        const int cur = kt & 1;
        if (kt + 1 < nk) { loadA(kt + 1); loadB(kt + 1); }
        #pragma unroll
        for (int kk = 0; kk < BK; ++kk) {
            const float* Ar = &As[cur][kk][ty * 4];
            const ulonglong2 alo = *reinterpret_cast<const ulonglong2*>(Ar);
            const ulonglong2 ahi = *reinterpret_cast<const ulonglong2*>(Ar + 64);
            unsigned long long ap[4] = {alo.x, alo.y, ahi.x, ahi.y};
            const float* Br = &Bs[cur][kk][tx * 4];
            unsigned long long bp[TN];
            #pragma unroll
            for (int c = 0; c < ((TN < 4) ? TN : 4); c++) bp[c] = pk2(Br[c], Br[c]);
            if constexpr (TN == 8) {
                #pragma unroll
                for (int c = 0; c < 4; c++) bp[4 + c] = pk2(Br[64 + c], Br[64 + c]);
            }
            #pragma unroll
            for (int p = 0; p < 4; p++)
                #pragma unroll
                for (int j = 0; j < TN; j++) fma2(acc2[p][j], ap[p], bp[j]);
        }
        if (kt + 1 < nk) stS(cur ^ 1);
        __syncthreads();
    }

    #pragma unroll
    for (int p = 0; p < 4; p++) {
        const int rbase = ty * 4 + (p & 1) * 2 + ((p >= 2) ? 64 : 0);
        #pragma unroll
        for (int j = 0; j < TN; j++) {
            const int col = tx * 4 + (j & 3) + ((j >= 4 && TN == 8) ? 64 : 0);
            const int n = n0 + col;
            const float2 f = upk2(acc2[p][j]);
            #pragma unroll
            for (int h = 0; h < 2; h++) {
                const int m = m0 + rbase + h;
                if (m >= M) continue;
                float v = h ? f.y : f.x;
                if constexpr (HASBIAS) v += bias[n];
                if constexpr (RELU)    v = fmaxf(v, 0.f);
                C[(long long)m * N + n] = v;
            }
        }
    }
}

// ---------------------------------------------------------------------------
// Branch0 first GEMM with on-the-fly pair A-tile, f32x2 mainloop.
// ---------------------------------------------------------------------------
__global__ void __launch_bounds__(256)
sgemm_pair_k(const float* __restrict__ sub, const float* __restrict__ B,
             const float* __restrict__ bias, float* __restrict__ C)
{
    constexpr int BM = 128, BN = 128, BK = 8, TN = 8, TX = 16;
    constexpr int K = C0, N = C1;

    const int tid = threadIdx.x;
    const int tx  = tid % TX;
    const int ty  = tid / TX;
    const int m0  = blockIdx.x * BM;

    __shared__ __align__(16) float As[2][BK][BM + 4];
    __shared__ __align__(16) float Bs[2][BK][BN];

    const int ar = tid >> 1;
    const int ak = (tid & 1) * 4;
    const int bk = tid >> 5;
    const int bc = (tid & 31) * 4;

    const int m = m0 + ar;
    const int pb = m / NN;
    const int pr = m - pb * NN;
    const int pi = pr / NTOK;
    const int pj = pr - pi * NTOK;
    const float* rowI = sub + (long long)(pb * NTOK + pi) * C0;
    const float* rowJ = sub + (long long)(pb * NTOK + pj) * C0;

    float aReg[4], bReg[4];
    unsigned long long acc2[4][TN];
    #pragma unroll
    for (int p = 0; p < 4; p++)
        #pragma unroll
        for (int j = 0; j < TN; j++) acc2[p][j] = 0ULL;

    constexpr int nk = K / BK;  // 32

    auto loadA = [&](int kt) {
        const int k = kt * BK + ak;
        const float4 va = *reinterpret_cast<const float4*>(rowI + k);
        const float4 vb = *reinterpret_cast<const float4*>(rowJ + k);
        aReg[0] = va.x * vb.x; aReg[1] = va.y * vb.y;
        aReg[2] = va.z * vb.z; aReg[3] = va.w * vb.w;
    };
    auto loadB = [&](int kt) {
        const int k = kt * BK + bk;
        const float4 v = *reinterpret_cast<const float4*>(B + (long long)k * N + bc);
        bReg[0] = v.x; bReg[1] = v.y; bReg[2] = v.z; bReg[3] = v.w;
    };
    auto stS = [&](int buf) {
        #pragma unroll
        for (int c = 0; c < 4; c++) As[buf][ak + c][ar] = aReg[c];
        #pragma unroll
        for (int c = 0; c < 4; c++) Bs[buf][bk][bc + c] = bReg[c];
    };

    loadA(0); loadB(0); stS(0);
    __syncthreads();

    for (int kt = 0; kt < nk; ++kt) {
        const int cur = kt & 1;
        if (kt + 1 < nk) { loadA(kt + 1); loadB(kt + 1); }
        #pragma unroll
        for (int kk = 0; kk < BK; ++kk) {
            const float* Ar = &As[cur][kk][ty * 4];
            const ulonglong2 alo = *reinterpret_cast<const ulonglong2*>(Ar);
            const ulonglong2 ahi = *reinterpret_cast<const ulonglong2*>(Ar + 64);
            unsigned long long ap[4] = {alo.x, alo.y, ahi.x, ahi.y};
            const float* Br = &Bs[cur][kk][tx * 4];
            unsigned long long bp[TN];
            #pragma unroll
            for (int c = 0; c < 4; c++) {
                bp[c]     = pk2(Br[c], Br[c]);
                bp[4 + c] = pk2(Br[64 + c], Br[64 + c]);
            }
            #pragma unroll
            for (int p = 0; p < 4; p++)
                #pragma unroll
                for (int j = 0; j < TN; j++) fma2(acc2[p][j], ap[p], bp[j]);
        }
        if (kt + 1 < nk) stS(cur ^ 1);
        __syncthreads();
    }

    #pragma unroll
    for (int p = 0; p < 4; p++) {
        const int rbase = ty * 4 + (p & 1) * 2 + ((p >= 2) ? 64 : 0);
        #pragma unroll
        for (int j = 0; j < TN; j++) {
            const int col = tx * 4 + (j & 3) + ((j >= 4) ? 64 : 0);
            const float2 f = upk2(acc2[p][j]);
            const long long mmA = m0 + rbase;
            C[mmA * N + col]       = fmaxf(f.x + bias[col], 0.f);
            C[(mmA + 1) * N + col] = fmaxf(f.y + bias[col], 0.f);
        }
    }
}

// ---------------------------------------------------------------------------
// Factorized conv1 (3x3, dil 1, 256->128, relu), f32x2 mainloop.
//   out[b,i,j,d] = relu(b1[d] + sum_{q,c} sub[b,j+q-1,c] * H_i[(q,c),d])
//   H_i[(q,c),d] = sum_p sub[b,i+p-1,c] * w1[p,q,c,d]   (computed in B loader)
// ---------------------------------------------------------------------------
__global__ void __launch_bounds__(256)
conv1f_k(const float* __restrict__ sub, const float* __restrict__ W,
         const float* __restrict__ bias, float* __restrict__ Out)
{
    constexpr int BM = 128, BN = 128, BK = 8, TN = 8, TX = 16;
    constexpr int K = 3 * C0;   // 768
    constexpr int nk = K / BK;  // 96

    const int tid = threadIdx.x;
    const int tx  = tid % TX;
    const int ty  = tid / TX;
    const int z   = blockIdx.z;           // b*196 + i
    const int b   = z / NTOK;
    const int i   = z - b * NTOK;
    const int m0  = blockIdx.x * BM;      // j tile base

    const float* subB = sub + (long long)b * NTOK * C0;

    __shared__ __align__(16) float As[2][BK][BM + 4];
    __shared__ __align__(16) float Bs[2][BK][BN];

    const int ar = tid >> 1;
    const int ak = (tid & 1) * 4;
    const int bk = tid >> 5;
    const int bc = (tid & 31) * 4;

    const bool pv0 = (i - 1 >= 0);
    const bool pv2 = (i + 1 < NTOK);
    const float* srow0 = subB + (i - 1) * C0;
    const float* srow1 = subB + i * C0;
    const float* srow2 = subB + (i + 1) * C0;

    float aReg[4], bReg[4];
    unsigned long long acc2[4][TN];
    #pragma unroll
    for (int p = 0; p < 4; p++)
        #pragma unroll
        for (int j = 0; j < TN; j++) acc2[p][j] = 0ULL;

    auto loadA = [&](int kt) {
        const int j = m0 + ar;
        const int k = kt * BK + ak;
        const int q = k >> 8;
        const int c = k & 255;
        const int jj = j + q - 1;
        if (j < NTOK && jj >= 0 && jj < NTOK) {
            const float4 v = *reinterpret_cast<const float4*>(subB + jj * C0 + c);
            aReg[0] = v.x; aReg[1] = v.y; aReg[2] = v.z; aReg[3] = v.w;
        } else {
            aReg[0] = aReg[1] = aReg[2] = aReg[3] = 0.f;
        }
    };
    auto loadB = [&](int kt) {
        const int k = kt * BK + bk;
        const int q = k >> 8;
        const int c = k & 255;
        float4 r = make_float4(0.f, 0.f, 0.f, 0.f);
        {
            const float s = srow1[c];
            const float4 w = *reinterpret_cast<const float4*>(W + ((size_t)(3 + q) * C0 + c) * C1 + bc);
            r.x = fmaf(s, w.x, r.x); r.y = fmaf(s, w.y, r.y);
            r.z = fmaf(s, w.z, r.z); r.w = fmaf(s, w.w, r.w);
        }
        if (pv0) {
            const float s = srow0[c];
            const float4 w = *reinterpret_cast<const float4*>(W + ((size_t)q * C0 + c) * C1 + bc);
            r.x = fmaf(s, w.x, r.x); r.y = fmaf(s, w.y, r.y);
            r.z = fmaf(s, w.z, r.z); r.w = fmaf(s, w.w, r.w);
        }
        if (pv2) {
            const float s = srow2[c];
            const float4 w = *reinterpret_cast<const float4*>(W + ((size_t)(6 + q) * C0 + c) * C1 + bc);
            r.x = fmaf(s, w.x, r.x); r.y = fmaf(s, w.y, r.y);
            r.z = fmaf(s, w.z, r.z); r.w = fmaf(s, w.w, r.w);
        }
        bReg[0] = r.x; bReg[1] = r.y; bReg[2] = r.z; bReg[3] = r.w;
    };
    auto stS = [&](int buf) {
        #pragma unroll
        for (int c = 0; c < 4; c++) As[buf][ak + c][ar] = aReg[c];
        #pragma unroll
        for (int c = 0; c < 4; c++) Bs[buf][bk][bc + c] = bReg[c];
    };

    loadA(0); loadB(0); stS(0);
    __syncthreads();

    for (int kt = 0; kt < nk; ++kt) {
        const int cur = kt & 1;
        if (kt + 1 < nk) { loadA(kt + 1); loadB(kt + 1); }
        #pragma unroll
        for (int kk = 0; kk < BK; ++kk) {
            const float* Ar = &As[cur][kk][ty * 4];
            const ulonglong2 alo = *reinterpret_cast<const ulonglong2*>(Ar);
            const ulonglong2 ahi = *reinterpret_cast<const ulonglong2*>(Ar + 64);
            unsigned long long ap[4] = {alo.x, alo.y, ahi.x, ahi.y};
            const float* Br = &Bs[cur][kk][tx * 4];
            unsigned long long bp[TN];
            #pragma unroll
            for (int c = 0; c < 4; c++) {
                bp[c]     = pk2(Br[c], Br[c]);
                bp[4 + c] = pk2(Br[64 + c], Br[64 + c]);
            }
            #pragma unroll
            for (int p = 0; p < 4; p++)
                #pragma unroll
                for (int j = 0; j < TN; j++) fma2(acc2[p][j], ap[p], bp[j]);
        }
        if (kt + 1 < nk) stS(cur ^ 1);
        __syncthreads();
    }

    #pragma unroll
    for (int p = 0; p < 4; p++) {
        const int rbase = ty * 4 + (p & 1) * 2 + ((p >= 2) ? 64 : 0);
        #pragma unroll
        for (int j = 0; j < TN; j++) {
            const int col = tx * 4 + (j & 3) + ((j >= 4) ? 64 : 0);
            const float2 f = upk2(acc2[p][j]);
            #pragma unroll
            for (int h = 0; h < 2; h++) {
                const int jrow = m0 + rbase + h;
                if (jrow >= NTOK) continue;
                const long long mm = (long long)b * NN + (long long)i * NTOK + jrow;
                Out[mm * C1 + col] = fmaxf((h ? f.y : f.x) + bias[col], 0.f);
            }
        }
    }
}

// ---------------------------------------------------------------------------
// Implicit-GEMM dilated 3x3 conv (conv2: 128->64, W-dil=2), f32x2 mainloop.
// ---------------------------------------------------------------------------
template<int CIN, int COUT, int DILW>
__global__ void __launch_bounds__(256)
conv_k(const float* __restrict__ In, const float* __restrict__ W,
       const float* __restrict__ bias, float* __restrict__ Out)
{
    constexpr int BM = 128, BK = 8;
    constexpr int BN = COUT;
    constexpr int TN = (COUT == 128) ? 8 : 4;
    constexpr int TX = BN / TN;
    constexpr int BLF = (BK * BN) / 256;
    constexpr int KT = CIN / BK;

    const int tid = threadIdx.x;
    const int tx  = tid % TX;
    const int ty  = tid / TX;
    const int m0  = blockIdx.x * BM;

    __shared__ __align__(16) float As[2][BK][BM + 4];
    __shared__ __align__(16) float Bs[2][BK][BN];
    __shared__ int   rowbase[BM];

    const int ar = tid >> 1;
    const int ak = (tid & 1) * 4;
    const int bk = tid >> 5;
    const int bc = (tid & 31) * BLF;

    int pb = 0, pi = 0, pj = 0;
    if (tid < BM) {
        const int m = m0 + tid;
        pb = m / NN;
        const int r = m - pb * NN;
        pi = r / NTOK;
        pj = r - pi * NTOK;
    }

    unsigned long long acc2[4][TN];
    #pragma unroll
    for (int p = 0; p < 4; p++)
        #pragma unroll
        for (int j = 0; j < TN; j++) acc2[p][j] = 0ULL;

    float aReg[4], bReg[BLF];

    auto loadA = [&](int kt) {
        const int base = rowbase[ar];
        const int k = kt * BK + ak;
        if (base >= 0) {
            const float4 v = *reinterpret_cast<const float4*>(In + base + k);
            aReg[0] = v.x; aReg[1] = v.y; aReg[2] = v.z; aReg[3] = v.w;
        } else {
            aReg[0] = aReg[1] = aReg[2] = aReg[3] = 0.f;
        }
    };

    for (int tap = 0; tap < 9; ++tap) {
        const int p = tap / 3 - 1;
        const int q = tap % 3 - 1;
        if (tid < BM) {
            const int ii = pi + p;
            const int jj = pj + q * DILW;
            rowbase[tid] = (ii >= 0 && ii < NTOK && jj >= 0 && jj < NTOK)
                         ? ((pb * NTOK + ii) * NTOK + jj) * CIN : -1;
        }
        __syncthreads();
        const float* Wt = W + tap * CIN * COUT;

        auto loadB = [&](int kt) {
            const int k = kt * BK + bk;
            if constexpr (BLF == 4) {
                const float4 v = *reinterpret_cast<const float4*>(Wt + k * COUT + bc);
                bReg[0] = v.x; bReg[1] = v.y; bReg[2] = v.z; bReg[3] = v.w;
            } else {
                const float2 v = *reinterpret_cast<const float2*>(Wt + k * COUT + bc);
                bReg[0] = v.x; bReg[1] = v.y;
            }
        };
        auto stS = [&](int buf) {
            #pragma unroll
            for (int c = 0; c < 4; c++) As[buf][ak + c][ar] = aReg[c];
            #pragma unroll
            for (int c = 0; c < BLF; c++) Bs[buf][bk][bc + c] = bReg[c];
        };

        loadA(0); loadB(0); stS(0);
        __syncthreads();

        for (int kt = 0; kt < KT; ++kt) {
            const int cur = kt & 1;
            if (kt + 1 < KT) { loadA(kt + 1); loadB(kt + 1); }
            #pragma unroll
            for (int kk = 0; kk < BK; ++kk) {
                const float* Ar = &As[cur][kk][ty * 4];
                const ulonglong2 alo = *reinterpret_cast<const ulonglong2*>(Ar);
                const ulonglong2 ahi = *reinterpret_cast<const ulonglong2*>(Ar + 64);
                unsigned long long ap[4] = {alo.x, alo.y, ahi.x, ahi.y};
                const float* Br = &Bs[cur][kk][tx * 4];
                unsigned long long bp[TN];
                #pragma unroll
                for (int c = 0; c < ((TN < 4) ? TN : 4); c++) bp[c] = pk2(Br[c], Br[c]);
                if constexpr (TN == 8) {
                    #pragma unroll
                    for (int c = 0; c < 4; c++) bp[4 + c] = pk2(Br[64 + c], Br[64 + c]);
                }
                #pragma unroll
                for (int pp = 0; pp < 4; pp++)
                    #pragma unroll
                    for (int j = 0; j < TN; j++) fma2(acc2[pp][j], ap[pp], bp[j]);
            }
            if (kt + 1 < KT) stS(cur ^ 1);
            __syncthreads();
        }
    }

    #pragma unroll
    for (int p = 0; p < 4; p++) {
        const int rbase = ty * 4 + (p & 1) * 2 + ((p >= 2) ? 64 : 0);
        #pragma unroll
        for (int j = 0; j < TN; j++) {
            const int col = tx * 4 + (j & 3) + ((j >= 4 && TN == 8) ? 64 : 0);
            const float2 f = upk2(acc2[p][j]);
            const long long mmA = m0 + rbase;
            Out[mmA * COUT + col]       = fmaxf(f.x + bias[col], 0.f);
            Out[(mmA + 1) * COUT + col] = fmaxf(f.y + bias[col], 0.f);
        }
    }
}

// ---------------------------------------------------------------------------
// Last conv (CIN=64 -> 1 channel, dil DILW): one warp per output pixel.
// ---------------------------------------------------------------------------
template<int CIN, int DILW>
__global__ void convlast_k(const float* __restrict__ In, const float* __restrict__ W,
                           const float* __restrict__ bias, float* __restrict__ Out)
{
    const int lane = threadIdx.x & 31;
    const int wp   = threadIdx.x >> 5;
    const int m    = blockIdx.x * 8 + wp;
    const int b = m / NN;
    const int r = m - b * NN;
    const int i = r / NTOK;
    const int j = r - i * NTOK;
    float acc = 0.f;
    #pragma unroll
    for (int tap = 0; tap < 9; ++tap) {
        const int p = tap / 3 - 1, q = tap % 3 - 1;
        const int ii = i + p, jj = j + q * DILW;
        if (ii >= 0 && ii < NTOK && jj >= 0 && jj < NTOK) {
            const float* src = In + (long long)((b * NTOK + ii) * NTOK + jj) * CIN;
            const float* w   = W + tap * CIN;
            acc = fmaf(src[lane],      w[lane],      acc);
            acc = fmaf(src[lane + 32], w[lane + 32], acc);
        }
    }
    #pragma unroll
    for (int off = 16; off; off >>= 1) acc += __shfl_xor_sync(0xffffffffu, acc, off);
    if (lane == 0) Out[m] = fmaxf(acc + bias[0], 0.f);
}

// branch0 third layer: relu(X[m,0:64] . w03 + b03), warp per pixel
__global__ void dot64_k(const float* __restrict__ X, const float* __restrict__ w,
                        const float* __restrict__ b, float* __restrict__ out)
{
    const int lane = threadIdx.x & 31;
    const int wp   = threadIdx.x >> 5;
    const int m    = blockIdx.x * 8 + wp;
    const float* src = X + (long long)m * 64;
    float acc = fmaf(src[lane], w[lane], src[lane + 32] * w[lane + 32]);
    #pragma unroll
    for (int off = 16; off; off >>= 1) acc += __shfl_xor_sync(0xffffffffu, acc, off);
    if (lane == 0) out[m] = fmaxf(acc + b[0], 0.f);
}

// softmax stats over symmetrized logits S[i,j] = L[i,j] + L[j,i], per batch
__global__ void smax_stats_k()
{
    const int b = blockIdx.x;
    const float* Lb = (blockIdx.y ? g_L1 : g_L0) + b * NN;
    __shared__ float red[256];
    const int tid = threadIdx.x;
    float mx = -1e30f;
    for (int idx = tid; idx < NN; idx += 256) {
        const int i = idx / NTOK, j = idx - (idx / NTOK) * NTOK;
        mx = fmaxf(mx, Lb[idx] + Lb[j * NTOK + i]);
    }
    red[tid] = mx; __syncthreads();
    for (int s = 128; s; s >>= 1) {
        if (tid < s) red[tid] = fmaxf(red[tid], red[tid + s]);
        __syncthreads();
    }
    mx = red[0]; __syncthreads();
    float sum = 0.f;
    for (int idx = tid; idx < NN; idx += 256) {
        const int i = idx / NTOK, j = idx - (idx / NTOK) * NTOK;
        sum += expf(Lb[idx] + Lb[j * NTOK + i] - mx);
    }
    red[tid] = sum; __syncthreads();
    for (int s = 128; s; s >>= 1) {
        if (tid < s) red[tid] += red[tid + s];
        __syncthreads();
    }
    if (tid == 0) {
        g_stats[(blockIdx.y * 8 + b) * 2]     = mx;
        g_stats[(blockIdx.y * 8 + b) * 2 + 1] = red[0];
    }
}

// Mc = 0.5 * (softmax0 + softmax1)
__global__ void combine_k()
{
    const int idx = blockIdx.x * 256 + threadIdx.x;
    if (idx >= MTOT) return;
    const int b = idx / NN;
    const int r = idx - b * NN;
    const int i = r / NTOK;
    const int j = r - i * NTOK;
    const int t = b * NN + j * NTOK + i;
    const float s0 = g_L0[idx] + g_L0[t];
    const float s1 = g_L1[idx] + g_L1[t];
    const float m0 = g_stats[b * 2],      z0 = g_stats[b * 2 + 1];
    const float m1 = g_stats[16 + b * 2], z1 = g_stats[16 + b * 2 + 1];
    g_Mc[idx] = 0.5f * (expf(s0 - m0) / z0 + expf(s1 - m1) / z1);
}

// ---------------------------------------------------------------------------
extern "C" void kernel_launch(void* const* d_in, const int* in_sizes, int n_in,
                              void* d_out, int out_size)
{
    (void)in_sizes; (void)n_in; (void)out_size;
    const float* x     = (const float*)d_in[0];
    const float* w_prj = (const float*)d_in[1];
    const float* b_prj = (const float*)d_in[2];
    const float* w01   = (const float*)d_in[3];
    const float* b01   = (const float*)d_in[4];
    const float* w02   = (const float*)d_in[5];
    const float* b02   = (const float*)d_in[6];
    const float* w03   = (const float*)d_in[7];
    const float* b03   = (const float*)d_in[8];
    const float* w1    = (const float*)d_in[9];
    const float* b1    = (const float*)d_in[10];
    const float* w2    = (const float*)d_in[11];
    const float* b2    = (const float*)d_in[12];
    const float* w3    = (const float*)d_in[13];
    const float* b3    = (const float*)d_in[14];
    float* out = (float*)d_out;

    float *sub, *s1, *s2, *L0, *L1, *Mc;
    cudaGetSymbolAddress((void**)&sub,  g_sub);
    cudaGetSymbolAddress((void**)&s1,   g_s1);
    cudaGetSymbolAddress((void**)&s2,   g_s2);
    cudaGetSymbolAddress((void**)&L0,   g_L0);
    cudaGetSymbolAddress((void**)&L1,   g_L1);
    cudaGetSymbolAddress((void**)&Mc,   g_Mc);

    // 1. projection: sub = x @ w_prj + b_prj
    sgemm_k<128, 8, false, true><<<dim3(13, 2, 1), 256>>>(
        x, w_prj, b_prj, sub, NBATCH * NTOK, INDIM, C0, 0, 0, 0);

    // 2. branch 0: pointwise chain (pair fused into first GEMM's A loader)
    sgemm_pair_k<<<MTOT / 128, 256>>>(sub, w01, b01, s1);
    sgemm_k<64, 4, true, true><<<dim3(MTOT / 128, 1, 1), 256>>>(
        s1, w02, b02, s2, MTOT, C1, C2, 0, 0, 0);
    dot64_k<<<MTOT / 8, 256>>>(s2, w03, b03, L0);

    // 3. branch 1: factorized conv1, then direct conv2/conv3
    conv1f_k<<<dim3(2, 1, NBATCH * NTOK), 256>>>(sub, w1, b1, s1);
    conv_k<128, 64, 2><<<MTOT / 128, 256>>>(s1, w2, b2, s2);
    convlast_k<64, 4><<<MTOT / 8, 256>>>(s2, w3, b3, L1);

    // 4. softmax (symmetrized) + combine maps
    smax_stats_k<<<dim3(8, 2), 256>>>();
    combine_k<<<(MTOT + 255) / 256, 256>>>();

    // 5. aggregation: out[b] = Mc[b] @ x[b]
    sgemm_k<128, 8, false, false><<<dim3(2, 16, 8), 256>>>(
        Mc, x, nullptr, out, NTOK, NTOK, INDIM,
        (long long)NN, (long long)NTOK * INDIM, (long long)NTOK * INDIM);
}

// round 4
// speedup vs baseline: 2.7900x; 1.6465x over previous
#include <cuda_runtime.h>
#include <math.h>

// ---------------------------------------------------------------------------
// Problem constants
// ---------------------------------------------------------------------------
namespace {
constexpr int NTOK   = 196;
constexpr int NBATCH = 8;
constexpr int NN     = NTOK * NTOK;        // 38416
constexpr int MTOT   = NBATCH * NN;        // 307328  (== 2401 * 128)
constexpr int INDIM  = 2048;
constexpr int C0     = 256;
constexpr int C1     = 128;
constexpr int C2     = 64;
}

// ---------------------------------------------------------------------------
// tf32 mma helpers
// ---------------------------------------------------------------------------
__device__ __forceinline__ unsigned cvt_tf32(float f) {
    unsigned r; asm("cvt.rna.tf32.f32 %0, %1;" : "=r"(r) : "f"(f)); return r;
}
__device__ __forceinline__ float tf32f(float f) {
    return __uint_as_float(cvt_tf32(f));
}
__device__ __forceinline__ void mma_tf32(float* d, const unsigned* a, const unsigned* b) {
    asm volatile(
        "mma.sync.aligned.m16n8k8.row.col.f32.tf32.tf32.f32 "
        "{%0,%1,%2,%3}, {%4,%5,%6,%7}, {%8,%9}, {%0,%1,%2,%3};"
        : "+f"(d[0]), "+f"(d[1]), "+f"(d[2]), "+f"(d[3])
        : "r"(a[0]), "r"(a[1]), "r"(a[2]), "r"(a[3]),
          "r"(b[0]), "r"(b[1]));
}
__device__ __forceinline__ unsigned fu(float f) { return __float_as_uint(f); }

// ---------------------------------------------------------------------------
// Scratch (static device globals; no runtime allocation)
// ---------------------------------------------------------------------------
__device__ float g_sub [NBATCH * NTOK * C0];          // 1.6 MB  [1568,256]
__device__ float g_s1  [(long long)MTOT * C1];        // 157 MB
__device__ float g_s2  [(long long)MTOT * C2];        //  79 MB
__device__ float g_L0  [MTOT];
__device__ float g_L1  [MTOT];
__device__ float g_Mc  [MTOT];
__device__ float g_stats[32];

// ---------------------------------------------------------------------------
// Generic guarded tf32 tensor-core GEMM: C = op(A[M,K] @ B[K,N] + bias).
// BM=128, BK=8. BN=128: warps 4x2 (warp tile 32x64). BN=64: warps 8x1 (16x64).
// ---------------------------------------------------------------------------
template<int BN, bool RELU, bool HASBIAS>
__global__ void __launch_bounds__(256)
gemm_tc(const float* __restrict__ A, const float* __restrict__ B,
        const float* __restrict__ bias, float* __restrict__ C,
        int M, int K, int N, long long sA, long long sB, long long sC)
{
    constexpr int BM = 128, BK = 8;
    constexpr int WN = (BN == 128) ? 2 : 1;
    constexpr int WM = 8 / WN;
    constexpr int MT = BM / (16 * WM);       // 2 (BN=128) or 1 (BN=64)
    constexpr int NT = BN / (8 * WN);        // 8
    constexpr int BLF = (BK * BN) / 256;     // 4 or 2
    constexpr int AP = BM + 8, BP = BN + 8;

    A += (long long)blockIdx.z * sA;
    B += (long long)blockIdx.z * sB;
    C += (long long)blockIdx.z * sC;

    const int tid  = threadIdx.x;
    const int wid  = tid >> 5, lane = tid & 31;
    const int lr   = lane >> 2, lc = lane & 3;
    const int wm   = (wid % WM) * (MT * 16);
    const int wn   = (wid / WM) * (NT * 8);
    const int m0   = blockIdx.x * BM;
    const int n0   = blockIdx.y * BN;

    __shared__ __align__(16) float As[2][BK][AP];
    __shared__ __align__(16) float Bs[2][BK][BP];

    const int ar = tid >> 1;
    const int ak = (tid & 1) * 4;
    const int bk = tid >> 5;
    const int bc = (tid & 31) * BLF;

    float aReg[4], bReg[BLF];
    float acc[MT][NT][4];
    #pragma unroll
    for (int mt = 0; mt < MT; mt++)
        #pragma unroll
        for (int nt = 0; nt < NT; nt++)
            #pragma unroll
            for (int c = 0; c < 4; c++) acc[mt][nt][c] = 0.f;

    const int nk = (K + BK - 1) / BK;

    auto loadA = [&](int kt) {
        const int m = m0 + ar;
        const int k = kt * BK + ak;
        if (m < M && (k + 3) < K) {
            const float4 v = *reinterpret_cast<const float4*>(A + (long long)m * K + k);
            aReg[0] = v.x; aReg[1] = v.y; aReg[2] = v.z; aReg[3] = v.w;
        } else {
            #pragma unroll
            for (int c = 0; c < 4; c++)
                aReg[c] = (m < M && (k + c) < K) ? A[(long long)m * K + k + c] : 0.f;
        }
    };
    auto loadB = [&](int kt) {
        const int k = kt * BK + bk;
        if (k < K) {
            if constexpr (BLF == 4) {
                const float4 v = *reinterpret_cast<const float4*>(B + (long long)k * N + n0 + bc);
                bReg[0] = v.x; bReg[1] = v.y; bReg[2] = v.z; bReg[3] = v.w;
            } else {
                const float2 v = *reinterpret_cast<const float2*>(B + (long long)k * N + n0 + bc);
                bReg[0] = v.x; bReg[1] = v.y;
            }
        } else {
            #pragma unroll
            for (int c = 0; c < BLF; c++) bReg[c] = 0.f;
        }
    };
    auto stS = [&](int buf) {
        #pragma unroll
        for (int c = 0; c < 4; c++) As[buf][ak + c][ar] = tf32f(aReg[c]);
        #pragma unroll
        for (int c = 0; c < BLF; c++) Bs[buf][bk][bc + c] = tf32f(bReg[c]);
    };

    loadA(0); loadB(0); stS(0);
    __syncthreads();

    for (int kt = 0; kt < nk; ++kt) {
        const int cur = kt & 1;
        if (kt + 1 < nk) { loadA(kt + 1); loadB(kt + 1); }
        unsigned af[MT][4], bf[NT][2];
        #pragma unroll
        for (int mt = 0; mt < MT; mt++) {
            const int r = wm + mt * 16 + lr;
            af[mt][0] = fu(As[cur][lc    ][r]);
            af[mt][1] = fu(As[cur][lc    ][r + 8]);
            af[mt][2] = fu(As[cur][lc + 4][r]);
            af[mt][3] = fu(As[cur][lc + 4][r + 8]);
        }
        #pragma unroll
        for (int nt = 0; nt < NT; nt++) {
            const int n = wn + nt * 8 + lr;
            bf[nt][0] = fu(Bs[cur][lc    ][n]);
            bf[nt][1] = fu(Bs[cur][lc + 4][n]);
        }
        #pragma unroll
        for (int mt = 0; mt < MT; mt++)
            #pragma unroll
            for (int nt = 0; nt < NT; nt++)
                mma_tf32(acc[mt][nt], af[mt], bf[nt]);
        if (kt + 1 < nk) stS(cur ^ 1);
        __syncthreads();
    }

    #pragma unroll
    for (int mt = 0; mt < MT; mt++)
        #pragma unroll
        for (int nt = 0; nt < NT; nt++) {
            const int col = n0 + wn + nt * 8 + 2 * lc;
            #pragma unroll
            for (int h = 0; h < 2; h++) {
                const int m = m0 + wm + mt * 16 + lr + h * 8;
                if (m >= M) continue;
                float v0 = acc[mt][nt][2 * h];
                float v1 = acc[mt][nt][2 * h + 1];
                if constexpr (HASBIAS) { v0 += bias[col]; v1 += bias[col + 1]; }
                if constexpr (RELU)    { v0 = fmaxf(v0, 0.f); v1 = fmaxf(v1, 0.f); }
                *reinterpret_cast<float2*>(C + (long long)m * N + col) = make_float2(v0, v1);
            }
        }
}

// ---------------------------------------------------------------------------
// Branch0 first GEMM with on-the-fly pair A-tile (tf32 TC).
// M=MTOT (no guards), K=256, N=128. C = relu(A @ w01 + b01).
// ---------------------------------------------------------------------------
__global__ void __launch_bounds__(256)
pair_tc(const float* __restrict__ sub, const float* __restrict__ B,
        const float* __restrict__ bias, float* __restrict__ C)
{
    constexpr int BM = 128, BN = 128, BK = 8;
    constexpr int MT = 2, NT = 8;
    constexpr int AP = BM + 8, BP = BN + 8;
    constexpr int K = C0, N = C1;
    constexpr int nk = K / BK;  // 32

    const int tid  = threadIdx.x;
    const int wid  = tid >> 5, lane = tid & 31;
    const int lr   = lane >> 2, lc = lane & 3;
    const int wm   = (wid % 4) * 32;
    const int wn   = (wid / 4) * 64;
    const int m0   = blockIdx.x * BM;

    __shared__ __align__(16) float As[2][BK][AP];
    __shared__ __align__(16) float Bs[2][BK][BP];

    const int ar = tid >> 1;
    const int ak = (tid & 1) * 4;
    const int bk = tid >> 5;
    const int bc = (tid & 31) * 4;

    const int m  = m0 + ar;
    const int pb = m / NN;
    const int pr = m - pb * NN;
    const int pi = pr / NTOK;
    const int pj = pr - pi * NTOK;
    const float* rowI = sub + (long long)(pb * NTOK + pi) * C0;
    const float* rowJ = sub + (long long)(pb * NTOK + pj) * C0;

    float aReg[4], bReg[4];
    float acc[MT][NT][4];
    #pragma unroll
    for (int mt = 0; mt < MT; mt++)
        #pragma unroll
        for (int nt = 0; nt < NT; nt++)
            #pragma unroll
            for (int c = 0; c < 4; c++) acc[mt][nt][c] = 0.f;

    auto loadA = [&](int kt) {
        const int k = kt * BK + ak;
        const float4 va = *reinterpret_cast<const float4*>(rowI + k);
        const float4 vb = *reinterpret_cast<const float4*>(rowJ + k);
        aReg[0] = va.x * vb.x; aReg[1] = va.y * vb.y;
        aReg[2] = va.z * vb.z; aReg[3] = va.w * vb.w;
    };
    auto loadB = [&](int kt) {
        const int k = kt * BK + bk;
        const float4 v = *reinterpret_cast<const float4*>(B + (long long)k * N + bc);
        bReg[0] = v.x; bReg[1] = v.y; bReg[2] = v.z; bReg[3] = v.w;
    };
    auto stS = [&](int buf) {
        #pragma unroll
        for (int c = 0; c < 4; c++) As[buf][ak + c][ar] = tf32f(aReg[c]);
        #pragma unroll
        for (int c = 0; c < 4; c++) Bs[buf][bk][bc + c] = tf32f(bReg[c]);
    };

    loadA(0); loadB(0); stS(0);
    __syncthreads();

    for (int kt = 0; kt < nk; ++kt) {
        const int cur = kt & 1;
        if (kt + 1 < nk) { loadA(kt + 1); loadB(kt + 1); }
        unsigned af[MT][4], bf[NT][2];
        #pragma unroll
        for (int mt = 0; mt < MT; mt++) {
            const int r = wm + mt * 16 + lr;
            af[mt][0] = fu(As[cur][lc    ][r]);
            af[mt][1] = fu(As[cur][lc    ][r + 8]);
            af[mt][2] = fu(As[cur][lc + 4][r]);
            af[mt][3] = fu(As[cur][lc + 4][r + 8]);
        }
        #pragma unroll
        for (int nt = 0; nt < NT; nt++) {
            const int n = wn + nt * 8 + lr;
            bf[nt][0] = fu(Bs[cur][lc    ][n]);
            bf[nt][1] = fu(Bs[cur][lc + 4][n]);
        }
        #pragma unroll
        for (int mt = 0; mt < MT; mt++)
            #pragma unroll
            for (int nt = 0; nt < NT; nt++)
                mma_tf32(acc[mt][nt], af[mt], bf[nt]);
        if (kt + 1 < nk) stS(cur ^ 1);
        __syncthreads();
    }

    #pragma unroll
    for (int mt = 0; mt < MT; mt++)
        #pragma unroll
        for (int nt = 0; nt < NT; nt++) {
            const int col = wn + nt * 8 + 2 * lc;
            #pragma unroll
            for (int h = 0; h < 2; h++) {
                const long long mm = m0 + wm + mt * 16 + lr + h * 8;
                float v0 = fmaxf(acc[mt][nt][2 * h]     + bias[col],     0.f);
                float v1 = fmaxf(acc[mt][nt][2 * h + 1] + bias[col + 1], 0.f);
                *reinterpret_cast<float2*>(C + mm * N + col) = make_float2(v0, v1);
            }
        }
}

// ---------------------------------------------------------------------------
// Factorized conv1 (3x3, dil 1, 256->128, relu), tf32 TC mainloop.
//   out[b,i,j,d] = relu(b1[d] + sum_{q,c} sub[b,j+q-1,c] * H_i[(q,c),d])
//   H_i[(q,c),d] = sum_p sub[b,i+p-1,c] * w1[p,q,c,d]   (computed in B loader)
// ---------------------------------------------------------------------------
__global__ void __launch_bounds__(256)
conv1f_tc(const float* __restrict__ sub, const float* __restrict__ W,
          const float* __restrict__ bias, float* __restrict__ Out)
{
    constexpr int BM = 128, BN = 128, BK = 8;
    constexpr int MT = 2, NT = 8;
    constexpr int AP = BM + 8, BP = BN + 8;
    constexpr int K = 3 * C0;   // 768
    constexpr int nk = K / BK;  // 96

    const int tid  = threadIdx.x;
    const int wid  = tid >> 5, lane = tid & 31;
    const int lr   = lane >> 2, lc = lane & 3;
    const int wm   = (wid % 4) * 32;
    const int wn   = (wid / 4) * 64;
    const int z    = blockIdx.z;           // b*196 + i
    const int b    = z / NTOK;
    const int i    = z - b * NTOK;
    const int m0   = blockIdx.x * BM;      // j tile base

    const float* subB = sub + (long long)b * NTOK * C0;

    __shared__ __align__(16) float As[2][BK][AP];
    __shared__ __align__(16) float Bs[2][BK][BP];

    const int ar = tid >> 1;
    const int ak = (tid & 1) * 4;
    const int bk = tid >> 5;
    const int bc = (tid & 31) * 4;

    const bool pv0 = (i - 1 >= 0);
    const bool pv2 = (i + 1 < NTOK);
    const float* srow0 = subB + (i - 1) * C0;
    const float* srow1 = subB + i * C0;
    const float* srow2 = subB + (i + 1) * C0;

    float aReg[4], bReg[4];
    float acc[MT][NT][4];
    #pragma unroll
    for (int mt = 0; mt < MT; mt++)
        #pragma unroll
        for (int nt = 0; nt < NT; nt++)
            #pragma unroll
            for (int c = 0; c < 4; c++) acc[mt][nt][c] = 0.f;

    auto loadA = [&](int kt) {
        const int j = m0 + ar;
        const int k = kt * BK + ak;
        const int q = k >> 8;
        const int c = k & 255;
        const int jj = j + q - 1;
        if (j < NTOK && jj >= 0 && jj < NTOK) {
            const float4 v = *reinterpret_cast<const float4*>(subB + jj * C0 + c);
            aReg[0] = v.x; aReg[1] = v.y; aReg[2] = v.z; aReg[3] = v.w;
        } else {
            aReg[0] = aReg[1] = aReg[2] = aReg[3] = 0.f;
        }
    };
    auto loadB = [&](int kt) {
        const int k = kt * BK + bk;
        const int q = k >> 8;
        const int c = k & 255;
        float4 r = make_float4(0.f, 0.f, 0.f, 0.f);
        {
            const float s = srow1[c];
            const float4 w = *reinterpret_cast<const float4*>(W + ((size_t)(3 + q) * C0 + c) * C1 + bc);
            r.x = fmaf(s, w.x, r.x); r.y = fmaf(s, w.y, r.y);
            r.z = fmaf(s, w.z, r.z); r.w = fmaf(s, w.w, r.w);
        }
        if (pv0) {
            const float s = srow0[c];
            const float4 w = *reinterpret_cast<const float4*>(W + ((size_t)q * C0 + c) * C1 + bc);
            r.x = fmaf(s, w.x, r.x); r.y = fmaf(s, w.y, r.y);
            r.z = fmaf(s, w.z, r.z); r.w = fmaf(s, w.w, r.w);
        }
        if (pv2) {
            const float s = srow2[c];
            const float4 w = *reinterpret_cast<const float4*>(W + ((size_t)(6 + q) * C0 + c) * C1 + bc);
            r.x = fmaf(s, w.x, r.x); r.y = fmaf(s, w.y, r.y);
            r.z = fmaf(s, w.z, r.z); r.w = fmaf(s, w.w, r.w);
        }
        bReg[0] = r.x; bReg[1] = r.y; bReg[2] = r.z; bReg[3] = r.w;
    };
    auto stS = [&](int buf) {
        #pragma unroll
        for (int c = 0; c < 4; c++) As[buf][ak + c][ar] = tf32f(aReg[c]);
        #pragma unroll
        for (int c = 0; c < 4; c++) Bs[buf][bk][bc + c] = tf32f(bReg[c]);
    };

    loadA(0); loadB(0); stS(0);
    __syncthreads();

    for (int kt = 0; kt < nk; ++kt) {
        const int cur = kt & 1;
        if (kt + 1 < nk) { loadA(kt + 1); loadB(kt + 1); }
        unsigned af[MT][4], bf[NT][2];
        #pragma unroll
        for (int mt = 0; mt < MT; mt++) {
            const int r = wm + mt * 16 + lr;
            af[mt][0] = fu(As[cur][lc    ][r]);
            af[mt][1] = fu(As[cur][lc    ][r + 8]);
            af[mt][2] = fu(As[cur][lc + 4][r]);
            af[mt][3] = fu(As[cur][lc + 4][r + 8]);
        }
        #pragma unroll
        for (int nt = 0; nt < NT; nt++) {
            const int n = wn + nt * 8 + lr;
            bf[nt][0] = fu(Bs[cur][lc    ][n]);
            bf[nt][1] = fu(Bs[cur][lc + 4][n]);
        }
        #pragma unroll
        for (int mt = 0; mt < MT; mt++)
            #pragma unroll
            for (int nt = 0; nt < NT; nt++)
                mma_tf32(acc[mt][nt], af[mt], bf[nt]);
        if (kt + 1 < nk) stS(cur ^ 1);
        __syncthreads();
    }

    #pragma unroll
    for (int mt = 0; mt < MT; mt++)
        #pragma unroll
        for (int nt = 0; nt < NT; nt++) {
            const int col = wn + nt * 8 + 2 * lc;
            #pragma unroll
            for (int h = 0; h < 2; h++) {
                const int j = m0 + wm + mt * 16 + lr + h * 8;
                if (j >= NTOK) continue;
                const long long mm = (long long)b * NN + (long long)i * NTOK + j;
                float v0 = fmaxf(acc[mt][nt][2 * h]     + bias[col],     0.f);
                float v1 = fmaxf(acc[mt][nt][2 * h + 1] + bias[col + 1], 0.f);
                *reinterpret_cast<float2*>(Out + mm * C1 + col) = make_float2(v0, v1);
            }
        }
}

// ---------------------------------------------------------------------------
// Implicit-GEMM dilated 3x3 conv (conv2: 128->64, W-dil=2), tf32 TC mainloop.
// ---------------------------------------------------------------------------
template<int CIN, int COUT, int DILW>
__global__ void __launch_bounds__(256)
conv_tc(const float* __restrict__ In, const float* __restrict__ W,
        const float* __restrict__ bias, float* __restrict__ Out)
{
    constexpr int BM = 128, BK = 8;
    constexpr int BN = COUT;                 // 64
    constexpr int MT = 1, NT = 8;            // warps 8x1, warp tile 16x64
    constexpr int AP = BM + 8, BP = BN + 8;
    constexpr int BLF = (BK * BN) / 256;     // 2
    constexpr int KT = CIN / BK;             // 16

    const int tid  = threadIdx.x;
    const int wid  = tid >> 5, lane = tid & 31;
    const int lr   = lane >> 2, lc = lane & 3;
    const int wm   = wid * 16;
    const int m0   = blockIdx.x * BM;

    __shared__ __align__(16) float As[2][BK][AP];
    __shared__ __align__(16) float Bs[2][BK][BP];
    __shared__ int rowbase[BM];

    const int ar = tid >> 1;
    const int ak = (tid & 1) * 4;
    const int bk = tid >> 5;
    const int bc = (tid & 31) * BLF;

    int pb = 0, pi = 0, pj = 0;
    if (tid < BM) {
        const int m = m0 + tid;
        pb = m / NN;
        const int r = m - pb * NN;
        pi = r / NTOK;
        pj = r - pi * NTOK;
    }

    float acc[MT][NT][4];
    #pragma unroll
    for (int mt = 0; mt < MT; mt++)
        #pragma unroll
        for (int nt = 0; nt < NT; nt++)
            #pragma unroll
            for (int c = 0; c < 4; c++) acc[mt][nt][c] = 0.f;

    float aReg[4], bReg[BLF];

    auto loadA = [&](int kt) {
        const int base = rowbase[ar];
        const int k = kt * BK + ak;
        if (base >= 0) {
            const float4 v = *reinterpret_cast<const float4*>(In + base + k);
            aReg[0] = v.x; aReg[1] = v.y; aReg[2] = v.z; aReg[3] = v.w;
        } else {
            aReg[0] = aReg[1] = aReg[2] = aReg[3] = 0.f;
        }
    };

    for (int tap = 0; tap < 9; ++tap) {
        const int p = tap / 3 - 1;
        const int q = tap % 3 - 1;
        if (tid < BM) {
            const int ii = pi + p;
            const int jj = pj + q * DILW;
            rowbase[tid] = (ii >= 0 && ii < NTOK && jj >= 0 && jj < NTOK)
                         ? ((pb * NTOK + ii) * NTOK + jj) * CIN : -1;
        }
        __syncthreads();
        const float* Wt = W + tap * CIN * COUT;

        auto loadB = [&](int kt) {
            const int k = kt * BK + bk;
            const float2 v = *reinterpret_cast<const float2*>(Wt + k * COUT + bc);
            bReg[0] = v.x; bReg[1] = v.y;
        };
        auto stS = [&](int buf) {
            #pragma unroll
            for (int c = 0; c < 4; c++) As[buf][ak + c][ar] = tf32f(aReg[c]);
            #pragma unroll
            for (int c = 0; c < BLF; c++) Bs[buf][bk][bc + c] = tf32f(bReg[c]);
        };

        loadA(0); loadB(0); stS(0);
        __syncthreads();

        for (int kt = 0; kt < KT; ++kt) {
            const int cur = kt & 1;
            if (kt + 1 < KT) { loadA(kt + 1); loadB(kt + 1); }
            unsigned af[4], bf[NT][2];
            {
                const int r = wm + lr;
                af[0] = fu(As[cur][lc    ][r]);
                af[1] = fu(As[cur][lc    ][r + 8]);
                af[2] = fu(As[cur][lc + 4][r]);
                af[3] = fu(As[cur][lc + 4][r + 8]);
            }
            #pragma unroll
            for (int nt = 0; nt < NT; nt++) {
                const int n = nt * 8 + lr;
                bf[nt][0] = fu(Bs[cur][lc    ][n]);
                bf[nt][1] = fu(Bs[cur][lc + 4][n]);
            }
            #pragma unroll
            for (int nt = 0; nt < NT; nt++)
                mma_tf32(acc[0][nt], af, bf[nt]);
            if (kt + 1 < KT) stS(cur ^ 1);
            __syncthreads();
        }
    }

    #pragma unroll
    for (int nt = 0; nt < NT; nt++) {
        const int col = nt * 8 + 2 * lc;
        #pragma unroll
        for (int h = 0; h < 2; h++) {
            const long long mm = m0 + wm + lr + h * 8;
            float v0 = fmaxf(acc[0][nt][2 * h]     + bias[col],     0.f);
            float v1 = fmaxf(acc[0][nt][2 * h + 1] + bias[col + 1], 0.f);
            *reinterpret_cast<float2*>(Out + mm * COUT + col) = make_float2(v0, v1);
        }
    }
}

// ---------------------------------------------------------------------------
// Last conv (CIN=64 -> 1 channel, dil DILW): one warp per output pixel.
// ---------------------------------------------------------------------------
template<int CIN, int DILW>
__global__ void convlast_k(const float* __restrict__ In, const float* __restrict__ W,
                           const float* __restrict__ bias, float* __restrict__ Out)
{
    const int lane = threadIdx.x & 31;
    const int wp   = threadIdx.x >> 5;
    const int m    = blockIdx.x * 8 + wp;
    const int b = m / NN;
    const int r = m - b * NN;
    const int i = r / NTOK;
    const int j = r - i * NTOK;
    float acc = 0.f;
    #pragma unroll
    for (int tap = 0; tap < 9; ++tap) {
        const int p = tap / 3 - 1, q = tap % 3 - 1;
        const int ii = i + p, jj = j + q * DILW;
        if (ii >= 0 && ii < NTOK && jj >= 0 && jj < NTOK) {
            const float* src = In + (long long)((b * NTOK + ii) * NTOK + jj) * CIN;
            const float* w   = W + tap * CIN;
            acc = fmaf(src[lane],      w[lane],      acc);
            acc = fmaf(src[lane + 32], w[lane + 32], acc);
        }
    }
    #pragma unroll
    for (int off = 16; off; off >>= 1) acc += __shfl_xor_sync(0xffffffffu, acc, off);
    if (lane == 0) Out[m] = fmaxf(acc + bias[0], 0.f);
}

// branch0 third layer: relu(X[m,0:64] . w03 + b03), warp per pixel
__global__ void dot64_k(const float* __restrict__ X, const float* __restrict__ w,
                        const float* __restrict__ b, float* __restrict__ out)
{
    const int lane = threadIdx.x & 31;
    const int wp   = threadIdx.x >> 5;
    const int m    = blockIdx.x * 8 + wp;
    const float* src = X + (long long)m * 64;
    float acc = fmaf(src[lane], w[lane], src[lane + 32] * w[lane + 32]);
    #pragma unroll
    for (int off = 16; off; off >>= 1) acc += __shfl_xor_sync(0xffffffffu, acc, off);
    if (lane == 0) out[m] = fmaxf(acc + b[0], 0.f);
}

// softmax stats over symmetrized logits S[i,j] = L[i,j] + L[j,i], per batch
__global__ void smax_stats_k()
{
    const int b = blockIdx.x;
    const float* Lb = (blockIdx.y ? g_L1 : g_L0) + b * NN;
    __shared__ float red[256];
    const int tid = threadIdx.x;
    float mx = -1e30f;
    for (int idx = tid; idx < NN; idx += 256) {
        const int i = idx / NTOK, j = idx - (idx / NTOK) * NTOK;
        mx = fmaxf(mx, Lb[idx] + Lb[j * NTOK + i]);
    }
    red[tid] = mx; __syncthreads();
    for (int s = 128; s; s >>= 1) {
        if (tid < s) red[tid] = fmaxf(red[tid], red[tid + s]);
        __syncthreads();
    }
    mx = red[0]; __syncthreads();
    float sum = 0.f;
    for (int idx = tid; idx < NN; idx += 256) {
        const int i = idx / NTOK, j = idx - (idx / NTOK) * NTOK;
        sum += expf(Lb[idx] + Lb[j * NTOK + i] - mx);
    }
    red[tid] = sum; __syncthreads();
    for (int s = 128; s; s >>= 1) {
        if (tid < s) red[tid] += red[tid + s];
        __syncthreads();
    }
    if (tid == 0) {
        g_stats[(blockIdx.y * 8 + b) * 2]     = mx;
        g_stats[(blockIdx.y * 8 + b) * 2 + 1] = red[0];
    }
}

// Mc = 0.5 * (softmax0 + softmax1)
__global__ void combine_k()
{
    const int idx = blockIdx.x * 256 + threadIdx.x;
    if (idx >= MTOT) return;
    const int b = idx / NN;
    const int r = idx - b * NN;
    const int i = r / NTOK;
    const int j = r - i * NTOK;
    const int t = b * NN + j * NTOK + i;
    const float s0 = g_L0[idx] + g_L0[t];
    const float s1 = g_L1[idx] + g_L1[t];
    const float m0 = g_stats[b * 2],      z0 = g_stats[b * 2 + 1];
    const float m1 = g_stats[16 + b * 2], z1 = g_stats[16 + b * 2 + 1];
    g_Mc[idx] = 0.5f * (expf(s0 - m0) / z0 + expf(s1 - m1) / z1);
}

// ---------------------------------------------------------------------------
extern "C" void kernel_launch(void* const* d_in, const int* in_sizes, int n_in,
                              void* d_out, int out_size)
{
    (void)in_sizes; (void)n_in; (void)out_size;
    const float* x     = (const float*)d_in[0];
    const float* w_prj = (const float*)d_in[1];
    const float* b_prj = (const float*)d_in[2];
    const float* w01   = (const float*)d_in[3];
    const float* b01   = (const float*)d_in[4];
    const float* w02   = (const float*)d_in[5];
    const float* b02   = (const float*)d_in[6];
    const float* w03   = (const float*)d_in[7];
    const float* b03   = (const float*)d_in[8];
    const float* w1    = (const float*)d_in[9];
    const float* b1    = (const float*)d_in[10];
    const float* w2    = (const float*)d_in[11];
    const float* b2    = (const float*)d_in[12];
    const float* w3    = (const float*)d_in[13];
    const float* b3    = (const float*)d_in[14];
    float* out = (float*)d_out;

    float *sub, *s1, *s2, *L0, *L1, *Mc;
    cudaGetSymbolAddress((void**)&sub,  g_sub);
    cudaGetSymbolAddress((void**)&s1,   g_s1);
    cudaGetSymbolAddress((void**)&s2,   g_s2);
    cudaGetSymbolAddress((void**)&L0,   g_L0);
    cudaGetSymbolAddress((void**)&L1,   g_L1);
    cudaGetSymbolAddress((void**)&Mc,   g_Mc);

    // 1. projection: sub = x @ w_prj + b_prj          [1568,2048]x[2048,256]
    gemm_tc<128, false, true><<<dim3(13, 2, 1), 256>>>(
        x, w_prj, b_prj, sub, NBATCH * NTOK, INDIM, C0, 0, 0, 0);

    // 2. branch 0: pointwise chain (pair fused into first GEMM's A loader)
    pair_tc<<<MTOT / 128, 256>>>(sub, w01, b01, s1);
    gemm_tc<64, true, true><<<dim3(MTOT / 128, 1, 1), 256>>>(
        s1, w02, b02, s2, MTOT, C1, C2, 0, 0, 0);
    dot64_k<<<MTOT / 8, 256>>>(s2, w03, b03, L0);

    // 3. branch 1: factorized conv1, then direct conv2/conv3
    conv1f_tc<<<dim3(2, 1, NBATCH * NTOK), 256>>>(sub, w1, b1, s1);
    conv_tc<128, 64, 2><<<MTOT / 128, 256>>>(s1, w2, b2, s2);
    convlast_k<64, 4><<<MTOT / 8, 256>>>(s2, w3, b3, L1);

    // 4. softmax (symmetrized) + combine maps
    smax_stats_k<<<dim3(8, 2), 256>>>();
    combine_k<<<(MTOT + 255) / 256, 256>>>();

    // 5. aggregation: out[b] = Mc[b] @ x[b]           [196,196]x[196,2048] x8
    gemm_tc<128, false, false><<<dim3(2, 16, 8), 256>>>(
        Mc, x, nullptr, out, NTOK, NTOK, INDIM,
        (long long)NN, (long long)NTOK * INDIM, (long long)NTOK * INDIM);
}

// round 5
// speedup vs baseline: 3.0152x; 1.0807x over previous
#include <cuda_runtime.h>
#include <math.h>

// ---------------------------------------------------------------------------
// Problem constants
// ---------------------------------------------------------------------------
namespace {
constexpr int NTOK   = 196;
constexpr int NBATCH = 8;
constexpr int NN     = NTOK * NTOK;        // 38416
constexpr int MTOT   = NBATCH * NN;        // 307328  (== 2401 * 128)
constexpr int INDIM  = 2048;
constexpr int C0     = 256;
constexpr int C1     = 128;
constexpr int C2     = 64;
}

// ---------------------------------------------------------------------------
// tf32 mma / ldmatrix helpers
// ---------------------------------------------------------------------------
__device__ __forceinline__ unsigned cvt_tf32(float f) {
    unsigned r; asm("cvt.rna.tf32.f32 %0, %1;" : "=r"(r) : "f"(f)); return r;
}
__device__ __forceinline__ float tf32f(float f) {
    return __uint_as_float(cvt_tf32(f));
}
__device__ __forceinline__ void mma_tf32(float* d, const unsigned* a, const unsigned* b) {
    asm volatile(
        "mma.sync.aligned.m16n8k8.row.col.f32.tf32.tf32.f32 "
        "{%0,%1,%2,%3}, {%4,%5,%6,%7}, {%8,%9}, {%0,%1,%2,%3};"
        : "+f"(d[0]), "+f"(d[1]), "+f"(d[2]), "+f"(d[3])
        : "r"(a[0]), "r"(a[1]), "r"(a[2]), "r"(a[3]),
          "r"(b[0]), "r"(b[1]));
}
__device__ __forceinline__ unsigned fu(float f) { return __float_as_uint(f); }
__device__ __forceinline__ void ldsm4(unsigned& r0, unsigned& r1, unsigned& r2, unsigned& r3,
                                      unsigned addr) {
    asm volatile("ldmatrix.sync.aligned.m8n8.x4.shared.b16 {%0,%1,%2,%3}, [%4];"
                 : "=r"(r0), "=r"(r1), "=r"(r2), "=r"(r3) : "r"(addr));
}

// ---------------------------------------------------------------------------
// Scratch
// ---------------------------------------------------------------------------
__device__ float g_sub [NBATCH * NTOK * C0];
__device__ float g_s1  [(long long)MTOT * C1];
__device__ float g_s2  [(long long)MTOT * C2];
__device__ float g_L0  [MTOT];
__device__ float g_L1  [MTOT];
__device__ float g_Mc  [MTOT];
__device__ float g_stats[32];

// ---------------------------------------------------------------------------
// Generic guarded tf32 TC GEMM (BN=128), used for projection + aggregation.
// ---------------------------------------------------------------------------
template<bool RELU, bool HASBIAS>
__global__ void __launch_bounds__(256)
gemm_tc(const float* __restrict__ A, const float* __restrict__ B,
        const float* __restrict__ bias, float* __restrict__ C,
        int M, int K, int N, long long sA, long long sB, long long sC)
{
    constexpr int BM = 128, BN = 128, BK = 8;
    constexpr int MT = 2, NT = 8;
    constexpr int AP = BM + 8, BP = BN + 8;

    A += (long long)blockIdx.z * sA;
    B += (long long)blockIdx.z * sB;
    C += (long long)blockIdx.z * sC;

    const int tid  = threadIdx.x;
    const int wid  = tid >> 5, lane = tid & 31;
    const int lr   = lane >> 2, lc = lane & 3;
    const int wm   = (wid % 4) * 32;
    const int wn   = (wid / 4) * 64;
    const int m0   = blockIdx.x * BM;
    const int n0   = blockIdx.y * BN;

    __shared__ __align__(16) float As[2][BK][AP];
    __shared__ __align__(16) float Bs[2][BK][BP];

    const int ar = tid >> 1;
    const int ak = (tid & 1) * 4;
    const int bk = tid >> 5;
    const int bc = (tid & 31) * 4;

    float aReg[4], bReg[4];
    float acc[MT][NT][4];
    #pragma unroll
    for (int mt = 0; mt < MT; mt++)
        #pragma unroll
        for (int nt = 0; nt < NT; nt++)
            #pragma unroll
            for (int c = 0; c < 4; c++) acc[mt][nt][c] = 0.f;

    const int nk = (K + BK - 1) / BK;

    auto loadA = [&](int kt) {
        const int m = m0 + ar;
        const int k = kt * BK + ak;
        if (m < M && (k + 3) < K) {
            const float4 v = *reinterpret_cast<const float4*>(A + (long long)m * K + k);
            aReg[0] = v.x; aReg[1] = v.y; aReg[2] = v.z; aReg[3] = v.w;
        } else {
            #pragma unroll
            for (int c = 0; c < 4; c++)
                aReg[c] = (m < M && (k + c) < K) ? A[(long long)m * K + k + c] : 0.f;
        }
    };
    auto loadB = [&](int kt) {
        const int k = kt * BK + bk;
        if (k < K) {
            const float4 v = *reinterpret_cast<const float4*>(B + (long long)k * N + n0 + bc);
            bReg[0] = v.x; bReg[1] = v.y; bReg[2] = v.z; bReg[3] = v.w;
        } else {
            #pragma unroll
            for (int c = 0; c < 4; c++) bReg[c] = 0.f;
        }
    };
    auto stS = [&](int buf) {
        #pragma unroll
        for (int c = 0; c < 4; c++) As[buf][ak + c][ar] = tf32f(aReg[c]);
        #pragma unroll
        for (int c = 0; c < 4; c++) Bs[buf][bk][bc + c] = tf32f(bReg[c]);
    };

    loadA(0); loadB(0); stS(0);
    __syncthreads();

    for (int kt = 0; kt < nk; ++kt) {
        const int cur = kt & 1;
        if (kt + 1 < nk) { loadA(kt + 1); loadB(kt + 1); }
        unsigned af[MT][4], bf[NT][2];
        #pragma unroll
        for (int mt = 0; mt < MT; mt++) {
            const int r = wm + mt * 16 + lr;
            af[mt][0] = fu(As[cur][lc    ][r]);
            af[mt][1] = fu(As[cur][lc    ][r + 8]);
            af[mt][2] = fu(As[cur][lc + 4][r]);
            af[mt][3] = fu(As[cur][lc + 4][r + 8]);
        }
        #pragma unroll
        for (int nt = 0; nt < NT; nt++) {
            const int n = wn + nt * 8 + lr;
            bf[nt][0] = fu(Bs[cur][lc    ][n]);
            bf[nt][1] = fu(Bs[cur][lc + 4][n]);
        }
        #pragma unroll
        for (int mt = 0; mt < MT; mt++)
            #pragma unroll
            for (int nt = 0; nt < NT; nt++)
                mma_tf32(acc[mt][nt], af[mt], bf[nt]);
        if (kt + 1 < nk) stS(cur ^ 1);
        __syncthreads();
    }

    #pragma unroll
    for (int mt = 0; mt < MT; mt++)
        #pragma unroll
        for (int nt = 0; nt < NT; nt++) {
            const int col = n0 + wn + nt * 8 + 2 * lc;
            #pragma unroll
            for (int h = 0; h < 2; h++) {
                const int m = m0 + wm + mt * 16 + lr + h * 8;
                if (m >= M) continue;
                float v0 = acc[mt][nt][2 * h];
                float v1 = acc[mt][nt][2 * h + 1];
                if constexpr (HASBIAS) { v0 += bias[col]; v1 += bias[col + 1]; }
                if constexpr (RELU)    { v0 = fmaxf(v0, 0.f); v1 = fmaxf(v1, 0.f); }
                *reinterpret_cast<float2*>(C + (long long)m * N + col) = make_float2(v0, v1);
            }
        }
}

// ---------------------------------------------------------------------------
// pair4_k: relu(pair @ w01 + b01). 128x128x256, 4 warps, warp tile 64x64,
// ldmatrix fragments, [row][k] 48B-stride smem.
// ---------------------------------------------------------------------------
__global__ void __launch_bounds__(128)
pair4_k(const float* __restrict__ sub, const float* __restrict__ W,
        const float* __restrict__ bias, float* __restrict__ C)
{
    constexpr int BM = 128, BN = 128, MT = 4, NT = 8;
    constexpr int nk = C0 / 8;   // 32

    __shared__ __align__(16) float As[2][BM][12];
    __shared__ __align__(16) float Bs[2][BN][12];

    const int tid = threadIdx.x, lane = tid & 31, wid = tid >> 5;
    const int lr = lane >> 2, lc = lane & 3;
    const int wm = (wid & 1) * 64;
    const int wn = (wid >> 1) * 64;
    const int m0 = blockIdx.x * BM;

    const int m  = m0 + tid;
    const int pb = m / NN;
    const int pr = m - pb * NN;
    const int pi = pr / NTOK;
    const int pj = pr - pi * NTOK;
    const float* rowI = sub + (long long)(pb * NTOK + pi) * C0;
    const float* rowJ = sub + (long long)(pb * NTOK + pj) * C0;

    const unsigned aB = (unsigned)__cvta_generic_to_shared(&As[0][0][0]);
    const unsigned bB = (unsigned)__cvta_generic_to_shared(&Bs[0][0][0]);
    const unsigned aOff = ((lane & 7) + ((lane & 8) ? 8 : 0)) * 48 + ((lane & 16) ? 16 : 0);
    const unsigned bOff = ((lane & 7) + ((lane & 16) ? 8 : 0)) * 48 + ((lane & 8) ? 16 : 0);

    float aReg[8], bReg[8];
    float acc[MT][NT][4];
    #pragma unroll
    for (int mt = 0; mt < MT; mt++)
        #pragma unroll
        for (int nt = 0; nt < NT; nt++)
            #pragma unroll
            for (int c = 0; c < 4; c++) acc[mt][nt][c] = 0.f;

    auto loadA = [&](int kt) {
        const int k = kt * 8;
        const float4 a0 = *reinterpret_cast<const float4*>(rowI + k);
        const float4 a1 = *reinterpret_cast<const float4*>(rowI + k + 4);
        const float4 b0 = *reinterpret_cast<const float4*>(rowJ + k);
        const float4 b1 = *reinterpret_cast<const float4*>(rowJ + k + 4);
        aReg[0] = a0.x * b0.x; aReg[1] = a0.y * b0.y; aReg[2] = a0.z * b0.z; aReg[3] = a0.w * b0.w;
        aReg[4] = a1.x * b1.x; aReg[5] = a1.y * b1.y; aReg[6] = a1.z * b1.z; aReg[7] = a1.w * b1.w;
    };
    auto loadB = [&](int kt) {
        const int k = kt * 8;
        #pragma unroll
        for (int kk = 0; kk < 8; kk++) bReg[kk] = W[(k + kk) * C1 + tid];
    };
    auto stS = [&](int buf) {
        float* ap = &As[buf][tid][0];
        *reinterpret_cast<float4*>(ap) =
            make_float4(tf32f(aReg[0]), tf32f(aReg[1]), tf32f(aReg[2]), tf32f(aReg[3]));
        *reinterpret_cast<float4*>(ap + 4) =
            make_float4(tf32f(aReg[4]), tf32f(aReg[5]), tf32f(aReg[6]), tf32f(aReg[7]));
        float* bp = &Bs[buf][tid][0];
        *reinterpret_cast<float4*>(bp) =
            make_float4(tf32f(bReg[0]), tf32f(bReg[1]), tf32f(bReg[2]), tf32f(bReg[3]));
        *reinterpret_cast<float4*>(bp + 4) =
            make_float4(tf32f(bReg[4]), tf32f(bReg[5]), tf32f(bReg[6]), tf32f(bReg[7]));
    };

    loadA(0); loadB(0); stS(0);
    __syncthreads();

    for (int kt = 0; kt < nk; ++kt) {
        const int cur = kt & 1;
        if (kt + 1 < nk) { loadA(kt + 1); loadB(kt + 1); }
        const unsigned aAddr = aB + cur * (BM * 48) + wm * 48 + aOff;
        const unsigned bAddr = bB + cur * (BN * 48) + wn * 48 + bOff;
        unsigned af[MT][4], bf[NT][2];
        #pragma unroll
        for (int mt = 0; mt < MT; mt++)
            ldsm4(af[mt][0], af[mt][1], af[mt][2], af[mt][3], aAddr + mt * 768);
        #pragma unroll
        for (int g = 0; g < NT / 2; g++) {
            unsigned r0, r1, r2, r3;
            ldsm4(r0, r1, r2, r3, bAddr + g * 768);
            bf[2 * g][0] = r0; bf[2 * g][1] = r1;
            bf[2 * g + 1][0] = r2; bf[2 * g + 1][1] = r3;
        }
        #pragma unroll
        for (int mt = 0; mt < MT; mt++)
            #pragma unroll
            for (int nt = 0; nt < NT; nt++)
                mma_tf32(acc[mt][nt], af[mt], bf[nt]);
        if (kt + 1 < nk) stS(cur ^ 1);
        __syncthreads();
    }

    #pragma unroll
    for (int mt = 0; mt < MT; mt++)
        #pragma unroll
        for (int nt = 0; nt < NT; nt++) {
            const int col = wn + nt * 8 + 2 * lc;
            #pragma unroll
            for (int h = 0; h < 2; h++) {
                const long long row = m0 + wm + mt * 16 + lr + h * 8;
                float v0 = fmaxf(acc[mt][nt][2 * h]     + bias[col],     0.f);
                float v1 = fmaxf(acc[mt][nt][2 * h + 1] + bias[col + 1], 0.f);
                *reinterpret_cast<float2*>(C + row * C1 + col) = make_float2(v0, v1);
            }
        }
}

// ---------------------------------------------------------------------------
// conv1f8_k: factorized conv1 (256->128, dil1). One block per (b,i): BM=256
// covers all j (196 used). 8 warps 4x2, warp tile 64x64, K=768.
// ---------------------------------------------------------------------------
__global__ void __launch_bounds__(256)
conv1f8_k(const float* __restrict__ sub, const float* __restrict__ W,
          const float* __restrict__ bias, float* __restrict__ Out)
{
    constexpr int BM = 256, BN = 128, MT = 4, NT = 8;
    constexpr int nk = (3 * C0) / 8;   // 96

    __shared__ __align__(16) float As[2][BM][12];
    __shared__ __align__(16) float Bs[2][BN][12];
    __shared__ float sR[3 * C0];

    const int tid = threadIdx.x, lane = tid & 31, wid = tid >> 5;
    const int lr = lane >> 2, lc = lane & 3;
    const int wm = (wid & 3) * 64;
    const int wn = (wid >> 2) * 64;
    const int z  = blockIdx.x;          // b*196 + i
    const int b  = z / NTOK;
    const int i  = z - b * NTOK;
    const float* subB = sub + (long long)b * NTOK * C0;

    // preload the three source rows (zero-padded)
    for (int idx = tid; idx < 3 * C0; idx += 256) {
        const int p = idx >> 8, c = idx & 255;
        const int ii = i + p - 1;
        sR[idx] = (ii >= 0 && ii < NTOK) ? subB[ii * C0 + c] : 0.f;
    }
    __syncthreads();

    const unsigned aB = (unsigned)__cvta_generic_to_shared(&As[0][0][0]);
    const unsigned bB = (unsigned)__cvta_generic_to_shared(&Bs[0][0][0]);
    const unsigned aOff = ((lane & 7) + ((lane & 8) ? 8 : 0)) * 48 + ((lane & 16) ? 16 : 0);
    const unsigned bOff = ((lane & 7) + ((lane & 16) ? 8 : 0)) * 48 + ((lane & 8) ? 16 : 0);

    float aReg[8], bReg[8];
    float acc[MT][NT][4];
    #pragma unroll
    for (int mt = 0; mt < MT; mt++)
        #pragma unroll
        for (int nt = 0; nt < NT; nt++)
            #pragma unroll
            for (int c = 0; c < 4; c++) acc[mt][nt][c] = 0.f;

    auto loadA = [&](int kt) {
        const int k = kt * 8;
        const int q = k >> 8;
        const int c = k & 255;
        const int jj = tid + q - 1;          // row j = tid
        if (tid < NTOK && jj >= 0 && jj < NTOK) {
            const float4 v0 = *reinterpret_cast<const float4*>(subB + jj * C0 + c);
            const float4 v1 = *reinterpret_cast<const float4*>(subB + jj * C0 + c + 4);
            aReg[0] = v0.x; aReg[1] = v0.y; aReg[2] = v0.z; aReg[3] = v0.w;
            aReg[4] = v1.x; aReg[5] = v1.y; aReg[6] = v1.z; aReg[7] = v1.w;
        } else {
            #pragma unroll
            for (int c2 = 0; c2 < 8; c2++) aReg[c2] = 0.f;
        }
    };
    auto loadB = [&](int kt) {               // only tid < 128 (d = tid)
        const int k = kt * 8;
        const int q = k >> 8;
        const int c = k & 255;
        #pragma unroll
        for (int kk = 0; kk < 8; kk++) {
            float h = 0.f;
            #pragma unroll
            for (int p = 0; p < 3; p++)
                h = fmaf(sR[p * C0 + c + kk],
                         W[((size_t)((3 * p + q) * C0 + c + kk)) * C1 + tid], h);
            bReg[kk] = h;
        }
    };
    auto stS = [&](int buf) {
        float* ap = &As[buf][tid][0];
        *reinterpret_cast<float4*>(ap) =
            make_float4(tf32f(aReg[0]), tf32f(aReg[1]), tf32f(aReg[2]), tf32f(aReg[3]));
        *reinterpret_cast<float4*>(ap + 4) =
            make_float4(tf32f(aReg[4]), tf32f(aReg[5]), tf32f(aReg[6]), tf32f(aReg[7]));
        if (tid < BN) {
            float* bp = &Bs[buf][tid][0];
            *reinterpret_cast<float4*>(bp) =
                make_float4(tf32f(bReg[0]), tf32f(bReg[1]), tf32f(bReg[2]), tf32f(bReg[3]));
            *reinterpret_cast<float4*>(bp + 4) =
                make_float4(tf32f(bReg[4]), tf32f(bReg[5]), tf32f(bReg[6]), tf32f(bReg[7]));
        }
    };

    loadA(0); if (tid < BN) loadB(0); stS(0);
    __syncthreads();

    for (int kt = 0; kt < nk; ++kt) {
        const int cur = kt & 1;
        if (kt + 1 < nk) { loadA(kt + 1); if (tid < BN) loadB(kt + 1); }
        const unsigned aAddr = aB + cur * (BM * 48) + wm * 48 + aOff;
        const unsigned bAddr = bB + cur * (BN * 48) + wn * 48 + bOff;
        unsigned af[MT][4], bf[NT][2];
        #pragma unroll
        for (int mt = 0; mt < MT; mt++)
            ldsm4(af[mt][0], af[mt][1], af[mt][2], af[mt][3], aAddr + mt * 768);
        #pragma unroll
        for (int g = 0; g < NT / 2; g++) {
            unsigned r0, r1, r2, r3;
            ldsm4(r0, r1, r2, r3, bAddr + g * 768);
            bf[2 * g][0] = r0; bf[2 * g][1] = r1;
            bf[2 * g + 1][0] = r2; bf[2 * g + 1][1] = r3;
        }
        #pragma unroll
        for (int mt = 0; mt < MT; mt++)
            #pragma unroll
            for (int nt = 0; nt < NT; nt++)
                mma_tf32(acc[mt][nt], af[mt], bf[nt]);
        if (kt + 1 < nk) stS(cur ^ 1);
        __syncthreads();
    }

    #pragma unroll
    for (int mt = 0; mt < MT; mt++)
        #pragma unroll
        for (int nt = 0; nt < NT; nt++) {
            const int col = wn + nt * 8 + 2 * lc;
            #pragma unroll
            for (int h = 0; h < 2; h++) {
                const int j = wm + mt * 16 + lr + h * 8;
                if (j >= NTOK) continue;
                const long long mm = (long long)b * NN + (long long)i * NTOK + j;
                float v0 = fmaxf(acc[mt][nt][2 * h]     + bias[col],     0.f);
                float v1 = fmaxf(acc[mt][nt][2 * h + 1] + bias[col + 1], 0.f);
                *reinterpret_cast<float2*>(Out + mm * C1 + col) = make_float2(v0, v1);
            }
        }
}

// ---------------------------------------------------------------------------
// conv24_k: conv2 (128->64, W-dil=2) as single K=1152 implicit GEMM.
// BM=128, BN=64, 4 warps 2x2, warp tile 64x32.
// ---------------------------------------------------------------------------
__global__ void __launch_bounds__(128)
conv24_k(const float* __restrict__ In, const float* __restrict__ W,
         const float* __restrict__ bias, float* __restrict__ Out)
{
    constexpr int BM = 128, BN = 64, MT = 4, NT = 4;
    constexpr int nk = (9 * C1) / 8;   // 144

    __shared__ __align__(16) float As[2][BM][12];
    __shared__ __align__(16) float Bs[2][BN][12];
    __shared__ int rowbase[9][BM];

    const int tid = threadIdx.x, lane = tid & 31, wid = tid >> 5;
    const int lr = lane >> 2, lc = lane & 3;
    const int wm = (wid & 1) * 64;
    const int wn = (wid >> 1) * 32;
    const int m0 = blockIdx.x * BM;

    {
        const int m = m0 + tid;
        const int pb = m / NN;
        const int r = m - pb * NN;
        const int pi = r / NTOK;
        const int pj = r - pi * NTOK;
        #pragma unroll
        for (int tap = 0; tap < 9; tap++) {
            const int p = tap / 3 - 1, q = tap % 3 - 1;
            const int ii = pi + p, jj = pj + q * 2;
            rowbase[tap][tid] = (ii >= 0 && ii < NTOK && jj >= 0 && jj < NTOK)
                              ? ((pb * NTOK + ii) * NTOK + jj) * C1 : -1;
        }
    }
    __syncthreads();

    const unsigned aB = (unsigned)__cvta_generic_to_shared(&As[0][0][0]);
    const unsigned bB = (unsigned)__cvta_generic_to_shared(&Bs[0][0][0]);
    const unsigned aOff = ((lane & 7) + ((lane & 8) ? 8 : 0)) * 48 + ((lane & 16) ? 16 : 0);
    const unsigned bOff = ((lane & 7) + ((lane & 16) ? 8 : 0)) * 48 + ((lane & 8) ? 16 : 0);

    float aReg[8], bReg[8];
    float acc[MT][NT][4];
    #pragma unroll
    for (int mt = 0; mt < MT; mt++)
        #pragma unroll
        for (int nt = 0; nt < NT; nt++)
            #pragma unroll
            for (int c = 0; c < 4; c++) acc[mt][nt][c] = 0.f;

    auto loadA = [&](int kt) {
        const int k = kt * 8;
        const int tap = k >> 7;
        const int c = k & 127;
        const int base = rowbase[tap][tid];
        if (base >= 0) {
            const float4 v0 = *reinterpret_cast<const float4*>(In + base + c);
            const float4 v1 = *reinterpret_cast<const float4*>(In + base + c + 4);
            aReg[0] = v0.x; aReg[1] = v0.y; aReg[2] = v0.z; aReg[3] = v0.w;
            aReg[4] = v1.x; aReg[5] = v1.y; aReg[6] = v1.z; aReg[7] = v1.w;
        } else {
            #pragma unroll
            for (int c2 = 0; c2 < 8; c2++) aReg[c2] = 0.f;
        }
    };
    auto loadB = [&](int kt) {          // tid < 64, d = tid
        const int k = kt * 8;
        const int tap = k >> 7;
        const int c = k & 127;
        #pragma unroll
        for (int kk = 0; kk < 8; kk++)
            bReg[kk] = W[((size_t)(tap * C1 + c + kk)) * C2 + tid];
    };
    auto stS = [&](int buf) {
        float* ap = &As[buf][tid][0];
        *reinterpret_cast<float4*>(ap) =
            make_float4(tf32f(aReg[0]), tf32f(aReg[1]), tf32f(aReg[2]), tf32f(aReg[3]));
        *reinterpret_cast<float4*>(ap + 4) =
            make_float4(tf32f(aReg[4]), tf32f(aReg[5]), tf32f(aReg[6]), tf32f(aReg[7]));
        if (tid < BN) {
            float* bp = &Bs[buf][tid][0];
            *reinterpret_cast<float4*>(bp) =
                make_float4(tf32f(bReg[0]), tf32f(bReg[1]), tf32f(bReg[2]), tf32f(bReg[3]));
            *reinterpret_cast<float4*>(bp + 4) =
                make_float4(tf32f(bReg[4]), tf32f(bReg[5]), tf32f(bReg[6]), tf32f(bReg[7]));
        }
    };

    loadA(0); if (tid < BN) loadB(0); stS(0);
    __syncthreads();

    for (int kt = 0; kt < nk; ++kt) {
        const int cur = kt & 1;
        if (kt + 1 < nk) { loadA(kt + 1); if (tid < BN) loadB(kt + 1); }
        const unsigned aAddr = aB + cur * (BM * 48) + wm * 48 + aOff;
        const unsigned bAddr = bB + cur * (BN * 48) + wn * 48 + bOff;
        unsigned af[MT][4], bf[NT][2];
        #pragma unroll
        for (int mt = 0; mt < MT; mt++)
            ldsm4(af[mt][0], af[mt][1], af[mt][2], af[mt][3], aAddr + mt * 768);
        #pragma unroll
        for (int g = 0; g < NT / 2; g++) {
            unsigned r0, r1, r2, r3;
            ldsm4(r0, r1, r2, r3, bAddr + g * 768);
            bf[2 * g][0] = r0; bf[2 * g][1] = r1;
            bf[2 * g + 1][0] = r2; bf[2 * g + 1][1] = r3;
        }
        #pragma unroll
        for (int mt = 0; mt < MT; mt++)
            #pragma unroll
            for (int nt = 0; nt < NT; nt++)
                mma_tf32(acc[mt][nt], af[mt], bf[nt]);
        if (kt + 1 < nk) stS(cur ^ 1);
        __syncthreads();
    }

    #pragma unroll
    for (int mt = 0; mt < MT; mt++)
        #pragma unroll
        for (int nt = 0; nt < NT; nt++) {
            const int col = wn + nt * 8 + 2 * lc;
            #pragma unroll
            for (int h = 0; h < 2; h++) {
                const long long row = m0 + wm + mt * 16 + lr + h * 8;
                float v0 = fmaxf(acc[mt][nt][2 * h]     + bias[col],     0.f);
                float v1 = fmaxf(acc[mt][nt][2 * h + 1] + bias[col + 1], 0.f);
                *reinterpret_cast<float2*>(Out + row * C2 + col) = make_float2(v0, v1);
            }
        }
}

// ---------------------------------------------------------------------------
// gemm64L0_k: L0 = relu( relu(s1 @ w02 + b02) . w03 + b03 ). 8 warps 16x64.
// ---------------------------------------------------------------------------
__global__ void __launch_bounds__(256)
gemm64L0_k(const float* __restrict__ A, const float* __restrict__ B,
           const float* __restrict__ bias, const float* __restrict__ w03,
           const float* __restrict__ b03, float* __restrict__ L0)
{
    constexpr int BM = 128, BN = 64, BK = 8;
    constexpr int NT = 8;
    constexpr int AP = BM + 8, BP = BN + 8;
    constexpr int K = C1, N = C2;
    constexpr int nk = K / BK;  // 16

    const int tid  = threadIdx.x;
    const int wid  = tid >> 5, lane = tid & 31;
    const int lr   = lane >> 2, lc = lane & 3;
    const int wm   = wid * 16;
    const int m0   = blockIdx.x * BM;

    __shared__ __align__(16) float As[2][BK][AP];
    __shared__ __align__(16) float Bs[2][BK][BP];

    const int ar = tid >> 1;
    const int ak = (tid & 1) * 4;
    const int bk = tid >> 5;
    const int bc = (tid & 31) * 2;

    float aReg[4], bReg[2];
    float acc[NT][4];
    #pragma unroll
    for (int nt = 0; nt < NT; nt++)
        #pragma unroll
        for (int c = 0; c < 4; c++) acc[nt][c] = 0.f;

    auto loadA = [&](int kt) {
        const int k = kt * BK + ak;
        const float4 v = *reinterpret_cast<const float4*>(A + (long long)(m0 + ar) * K + k);
        aReg[0] = v.x; aReg[1] = v.y; aReg[2] = v.z; aReg[3] = v.w;
    };
    auto loadB = [&](int kt) {
        const int k = kt * BK + bk;
        const float2 v = *reinterpret_cast<const float2*>(B + (long long)k * N + bc);
        bReg[0] = v.x; bReg[1] = v.y;
    };
    auto stS = [&](int buf) {
        #pragma unroll
        for (int c = 0; c < 4; c++) As[buf][ak + c][ar] = tf32f(aReg[c]);
        #pragma unroll
        for (int c = 0; c < 2; c++) Bs[buf][bk][bc + c] = tf32f(bReg[c]);
    };

    loadA(0); loadB(0); stS(0);
    __syncthreads();

    for (int kt = 0; kt < nk; ++kt) {
        const int cur = kt & 1;
        if (kt + 1 < nk) { loadA(kt + 1); loadB(kt + 1); }
        unsigned af[4], bf[NT][2];
        {
            const int r = wm + lr;
            af[0] = fu(As[cur][lc    ][r]);
            af[1] = fu(As[cur][lc    ][r + 8]);
            af[2] = fu(As[cur][lc + 4][r]);
            af[3] = fu(As[cur][lc + 4][r + 8]);
        }
        #pragma unroll
        for (int nt = 0; nt < NT; nt++) {
            const int n = nt * 8 + lr;
            bf[nt][0] = fu(Bs[cur][lc    ][n]);
            bf[nt][1] = fu(Bs[cur][lc + 4][n]);
        }
        #pragma unroll
        for (int nt = 0; nt < NT; nt++)
            mma_tf32(acc[nt], af, bf[nt]);
        if (kt + 1 < nk) stS(cur ^ 1);
        __syncthreads();
    }

    // epilogue: relu(+b02), dot with w03, reduce over lc lanes, relu(+b03)
    float part0 = 0.f, part1 = 0.f;
    #pragma unroll
    for (int nt = 0; nt < NT; nt++) {
        const int col = nt * 8 + 2 * lc;
        const float w0 = w03[col], w1v = w03[col + 1];
        part0 += fmaxf(acc[nt][0] + bias[col], 0.f) * w0
               + fmaxf(acc[nt][1] + bias[col + 1], 0.f) * w1v;
        part1 += fmaxf(acc[nt][2] + bias[col], 0.f) * w0
               + fmaxf(acc[nt][3] + bias[col + 1], 0.f) * w1v;
    }
    part0 += __shfl_xor_sync(0xffffffffu, part0, 1);
    part0 += __shfl_xor_sync(0xffffffffu, part0, 2);
    part1 += __shfl_xor_sync(0xffffffffu, part1, 1);
    part1 += __shfl_xor_sync(0xffffffffu, part1, 2);
    if (lc == 0) {
        L0[m0 + wm + lr]     = fmaxf(part0 + b03[0], 0.f);
        L0[m0 + wm + lr + 8] = fmaxf(part1 + b03[0], 0.f);
    }
}

// ---------------------------------------------------------------------------
// Last conv (64 -> 1, dil 4): one warp per output pixel.
// ---------------------------------------------------------------------------
template<int CIN, int DILW>
__global__ void convlast_k(const float* __restrict__ In, const float* __restrict__ W,
                           const float* __restrict__ bias, float* __restrict__ Out)
{
    const int lane = threadIdx.x & 31;
    const int wp   = threadIdx.x >> 5;
    const int m    = blockIdx.x * 8 + wp;
    const int b = m / NN;
    const int r = m - b * NN;
    const int i = r / NTOK;
    const int j = r - i * NTOK;
    float acc = 0.f;
    #pragma unroll
    for (int tap = 0; tap < 9; ++tap) {
        const int p = tap / 3 - 1, q = tap % 3 - 1;
        const int ii = i + p, jj = j + q * DILW;
        if (ii >= 0 && ii < NTOK && jj >= 0 && jj < NTOK) {
            const float* src = In + (long long)((b * NTOK + ii) * NTOK + jj) * CIN;
            const float* w   = W + tap * CIN;
            acc = fmaf(src[lane],      w[lane],      acc);
            acc = fmaf(src[lane + 32], w[lane + 32], acc);
        }
    }
    #pragma unroll
    for (int off = 16; off; off >>= 1) acc += __shfl_xor_sync(0xffffffffu, acc, off);
    if (lane == 0) Out[m] = fmaxf(acc + bias[0], 0.f);
}

// softmax stats over symmetrized logits, per batch
__global__ void smax_stats_k()
{
    const int b = blockIdx.x;
    const float* Lb = (blockIdx.y ? g_L1 : g_L0) + b * NN;
    __shared__ float red[256];
    const int tid = threadIdx.x;
    float mx = -1e30f;
    for (int idx = tid; idx < NN; idx += 256) {
        const int i = idx / NTOK, j = idx - (idx / NTOK) * NTOK;
        mx = fmaxf(mx, Lb[idx] + Lb[j * NTOK + i]);
    }
    red[tid] = mx; __syncthreads();
    for (int s = 128; s; s >>= 1) {
        if (tid < s) red[tid] = fmaxf(red[tid], red[tid + s]);
        __syncthreads();
    }
    mx = red[0]; __syncthreads();
    float sum = 0.f;
    for (int idx = tid; idx < NN; idx += 256) {
        const int i = idx / NTOK, j = idx - (idx / NTOK) * NTOK;
        sum += expf(Lb[idx] + Lb[j * NTOK + i] - mx);
    }
    red[tid] = sum; __syncthreads();
    for (int s = 128; s; s >>= 1) {
        if (tid < s) red[tid] += red[tid + s];
        __syncthreads();
    }
    if (tid == 0) {
        g_stats[(blockIdx.y * 8 + b) * 2]     = mx;
        g_stats[(blockIdx.y * 8 + b) * 2 + 1] = red[0];
    }
}

// Mc = 0.5 * (softmax0 + softmax1)
__global__ void combine_k()
{
    const int idx = blockIdx.x * 256 + threadIdx.x;
    if (idx >= MTOT) return;
    const int b = idx / NN;
    const int r = idx - b * NN;
    const int i = r / NTOK;
    const int j = r - i * NTOK;
    const int t = b * NN + j * NTOK + i;
    const float s0 = g_L0[idx] + g_L0[t];
    const float s1 = g_L1[idx] + g_L1[t];
    const float m0 = g_stats[b * 2],      z0 = g_stats[b * 2 + 1];
    const float m1 = g_stats[16 + b * 2], z1 = g_stats[16 + b * 2 + 1];
    g_Mc[idx] = 0.5f * (expf(s0 - m0) / z0 + expf(s1 - m1) / z1);
}

// ---------------------------------------------------------------------------
extern "C" void kernel_launch(void* const* d_in, const int* in_sizes, int n_in,
                              void* d_out, int out_size)
{
    (void)in_sizes; (void)n_in; (void)out_size;
    const float* x     = (const float*)d_in[0];
    const float* w_prj = (const float*)d_in[1];
    const float* b_prj = (const float*)d_in[2];
    const float* w01   = (const float*)d_in[3];
    const float* b01   = (const float*)d_in[4];
    const float* w02   = (const float*)d_in[5];
    const float* b02   = (const float*)d_in[6];
    const float* w03   = (const float*)d_in[7];
    const float* b03   = (const float*)d_in[8];
    const float* w1    = (const float*)d_in[9];
    const float* b1    = (const float*)d_in[10];
    const float* w2    = (const float*)d_in[11];
    const float* b2    = (const float*)d_in[12];
    const float* w3    = (const float*)d_in[13];
    const float* b3    = (const float*)d_in[14];
    float* out = (float*)d_out;

    float *sub, *s1, *s2, *L0, *L1, *Mc;
    cudaGetSymbolAddress((void**)&sub,  g_sub);
    cudaGetSymbolAddress((void**)&s1,   g_s1);
    cudaGetSymbolAddress((void**)&s2,   g_s2);
    cudaGetSymbolAddress((void**)&L0,   g_L0);
    cudaGetSymbolAddress((void**)&L1,   g_L1);
    cudaGetSymbolAddress((void**)&Mc,   g_Mc);

    // 1. projection
    gemm_tc<false, true><<<dim3(13, 2, 1), 256>>>(
        x, w_prj, b_prj, sub, NBATCH * NTOK, INDIM, C0, 0, 0, 0);

    // 2. branch 0
    pair4_k<<<MTOT / 128, 128>>>(sub, w01, b01, s1);
    gemm64L0_k<<<MTOT / 128, 256>>>(s1, w02, b02, w03, b03, L0);

    // 3. branch 1
    conv1f8_k<<<NBATCH * NTOK, 256>>>(sub, w1, b1, s1);
    conv24_k<<<MTOT / 128, 128>>>(s1, w2, b2, s2);
    convlast_k<64, 4><<<MTOT / 8, 256>>>(s2, w3, b3, L1);

    // 4. softmax + combine
    smax_stats_k<<<dim3(8, 2), 256>>>();
    combine_k<<<(MTOT + 255) / 256, 256>>>();

    // 5. aggregation
    gemm_tc<false, false><<<dim3(2, 16, 8), 256>>>(
        Mc, x, nullptr, out, NTOK, NTOK, INDIM,
        (long long)NN, (long long)NTOK * INDIM, (long long)NTOK * INDIM);
}